// round 7
// baseline (speedup 1.0000x reference)
#include <cuda_runtime.h>
#include <cuda_bf16.h>
#include <math.h>
#include <stdint.h>

#define DD 1024
#define BSZ 256

// ---- scratch globals --------------------------------------------------------
__device__ float g_h[BSZ * DD];
__device__ float g_logits[BSZ * DD];
__device__ float g_text2[BSZ * DD];
__device__ __nv_bfloat16 g_pretxt_h[BSZ * DD];
__device__ __nv_bfloat16 g_pimgb_h[BSZ * DD];
__device__ __nv_bfloat16 g_rw2_h[DD * DD];   // rw2 bf16, [k][n]

// ---- cp.async helpers ------------------------------------------------------
#define CP_ASYNC16(dst, src) \
    asm volatile("cp.async.cg.shared.global [%0], [%1], 16;" \
        :: "r"(dst), "l"(src) : "memory")
#define CP_COMMIT() asm volatile("cp.async.commit_group;" ::: "memory")
#define CP_WAIT0()  asm volatile("cp.async.wait_group 0;" ::: "memory")

// ============================================================================
// Small-chain fp32 GEMMs (unchanged — known good):
// 64x64 tile, BK=32, double-buffered, register prefetch, one sync per chunk.
// ============================================================================
template <bool RELU, bool HAS_BIAS, bool BF16OUT>
__device__ __forceinline__ void gemm64_body(
    const float* __restrict__ A, const float* __restrict__ B,
    const float* __restrict__ bias, void* __restrict__ Cv, float* smem)
{
    const int AS  = 32 * 68;
    const int BS_ = 32 * 64;
    const int STG = AS + BS_;

    const int t  = threadIdx.x;
    const int m0 = blockIdx.y * 64;
    const int n0 = blockIdx.x * 64;
    const int tx = t & 15, ty = t >> 4;

    const int ar  = t & 63;
    const int akv = (t >> 6) * 8;
    const int bk  = t >> 3;
    const int bnv = (t & 7) * 8;

    const float* Arow = A + (size_t)(m0 + ar) * DD + akv;
    const float* Brow = B + (size_t)bk * DD + n0 + bnv;

    float4 a0, a1, b0, b1;
    a0 = *(const float4*)(Arow);
    a1 = *(const float4*)(Arow + 4);
    b0 = *(const float4*)(Brow);
    b1 = *(const float4*)(Brow + 4);
    {
        float* Ad = smem;
        float* Bd = smem + AS;
        Ad[(akv + 0) * 68 + ar] = a0.x; Ad[(akv + 1) * 68 + ar] = a0.y;
        Ad[(akv + 2) * 68 + ar] = a0.z; Ad[(akv + 3) * 68 + ar] = a0.w;
        Ad[(akv + 4) * 68 + ar] = a1.x; Ad[(akv + 5) * 68 + ar] = a1.y;
        Ad[(akv + 6) * 68 + ar] = a1.z; Ad[(akv + 7) * 68 + ar] = a1.w;
        *(float4*)(&Bd[bk * 64 + bnv])     = b0;
        *(float4*)(&Bd[bk * 64 + bnv + 4]) = b1;
    }
    __syncthreads();

    float acc[4][4] = {};

    for (int c = 0; c < 32; c++) {
        const int s = c & 1;
        const float* As = smem + s * STG;
        const float* Bs = smem + s * STG + AS;
        const int kn = (c + 1) * 32;

        if (c < 31) {
            a0 = *(const float4*)(Arow + kn);
            a1 = *(const float4*)(Arow + kn + 4);
            b0 = *(const float4*)(Brow + (size_t)kn * DD);
            b1 = *(const float4*)(Brow + (size_t)kn * DD + 4);
        }

        #pragma unroll
        for (int kk = 0; kk < 32; kk++) {
            float a[4], b[4];
            *(float4*)a = *(const float4*)(&As[kk * 68 + ty * 4]);
            *(float4*)b = *(const float4*)(&Bs[kk * 64 + tx * 4]);
            #pragma unroll
            for (int r = 0; r < 4; r++)
                #pragma unroll
                for (int cc = 0; cc < 4; cc++)
                    acc[r][cc] = fmaf(a[r], b[cc], acc[r][cc]);
        }

        if (c < 31) {
            float* Ad = smem + (s ^ 1) * STG;
            float* Bd = Ad + AS;
            Ad[(akv + 0) * 68 + ar] = a0.x; Ad[(akv + 1) * 68 + ar] = a0.y;
            Ad[(akv + 2) * 68 + ar] = a0.z; Ad[(akv + 3) * 68 + ar] = a0.w;
            Ad[(akv + 4) * 68 + ar] = a1.x; Ad[(akv + 5) * 68 + ar] = a1.y;
            Ad[(akv + 6) * 68 + ar] = a1.z; Ad[(akv + 7) * 68 + ar] = a1.w;
            *(float4*)(&Bd[bk * 64 + bnv])     = b0;
            *(float4*)(&Bd[bk * 64 + bnv + 4]) = b1;
        }
        __syncthreads();
    }

    #pragma unroll
    for (int r = 0; r < 4; r++) {
        const int m = m0 + ty * 4 + r;
        #pragma unroll
        for (int c = 0; c < 4; c++) {
            const int n = n0 + tx * 4 + c;
            float v = acc[r][c];
            if (HAS_BIAS) v += bias[n];
            if (RELU) v = fmaxf(v, 0.0f);
            if (BF16OUT)
                ((__nv_bfloat16*)Cv)[(size_t)m * DD + n] = __float2bfloat16(v);
            else
                ((float*)Cv)[(size_t)m * DD + n] = v;
        }
    }
}

#define SMALL_SMEM (2 * (32 * 68 + 32 * 64) * (int)sizeof(float))

__global__ void __launch_bounds__(256)
small_pair(const float* __restrict__ text, const float* __restrict__ aw1,
           const float* __restrict__ ab1, float* __restrict__ h,
           const float* __restrict__ image, const float* __restrict__ rw1,
           const float* __restrict__ rb1, __nv_bfloat16* __restrict__ pimgb)
{
    extern __shared__ float smemf[];
    if (blockIdx.z == 0)
        gemm64_body<true, true, false>(text, aw1, ab1, h, smemf);
    else
        gemm64_body<false, true, true>(image, rw1, rb1, pimgb, smemf);
}

__global__ void __launch_bounds__(256)
small_logits(const float* __restrict__ h, const float* __restrict__ aw2,
             const float* __restrict__ ab2, float* __restrict__ logits)
{
    extern __shared__ float smemf[];
    gemm64_body<false, true, false>(h, aw2, ab2, logits, smemf);
}

__global__ void __launch_bounds__(256)
small_pretxt(const float* __restrict__ text2, const float* __restrict__ rw1b,
             __nv_bfloat16* __restrict__ pretxt)
{
    extern __shared__ float smemf[];
    gemm64_body<false, false, true>(text2, rw1b, nullptr, pretxt, smemf);
}

// ---------------------------------------------------------------------------
__global__ void __launch_bounds__(256)
convert_rw2(const float* __restrict__ in, __nv_bfloat16* __restrict__ out)
{
    const int idx = (blockIdx.x * 256 + threadIdx.x) * 4;
    float4 v = *(const float4*)(in + idx);
    __nv_bfloat16 o[4] = {
        __float2bfloat16(v.x), __float2bfloat16(v.y),
        __float2bfloat16(v.z), __float2bfloat16(v.w)};
    *(uint2*)(out + idx) = *(uint2*)o;
}

// ---------------------------------------------------------------------------
__global__ void __launch_bounds__(256)
softmax_mul(const float* __restrict__ logits, const float* __restrict__ text,
            float* __restrict__ out)
{
    const int row = blockIdx.x;
    const int t   = threadIdx.x;
    const float* l = logits + (size_t)row * DD;
    __shared__ float smax[8];
    __shared__ float ssum[8];

    float m = -1e30f;
    #pragma unroll
    for (int k = t; k < DD; k += 256) m = fmaxf(m, l[k]);
    #pragma unroll
    for (int o = 16; o > 0; o >>= 1)
        m = fmaxf(m, __shfl_xor_sync(0xffffffffu, m, o));
    if ((t & 31) == 0) smax[t >> 5] = m;
    __syncthreads();
    float rowmax = smax[0];
    #pragma unroll
    for (int w = 1; w < 8; w++) rowmax = fmaxf(rowmax, smax[w]);

    float s = 0.0f;
    #pragma unroll
    for (int k = t; k < DD; k += 256) s += expf(l[k] - rowmax);
    #pragma unroll
    for (int o = 16; o > 0; o >>= 1)
        s += __shfl_xor_sync(0xffffffffu, s, o);
    if ((t & 31) == 0) ssum[t >> 5] = s;
    __syncthreads();
    float tot = 0.0f;
    #pragma unroll
    for (int w = 0; w < 8; w++) tot += ssum[w];
    const float inv = 1.0f / tot;

    const float* tr = text + (size_t)row * DD;
    float* orow = out + (size_t)row * DD;
    #pragma unroll
    for (int k = t; k < DD; k += 256)
        orow[k] = tr[k] * (expf(l[k] - rowmax) * inv);
}

// ============================================================================
// Big GEMM on mma.sync (bf16, fp32 accum).
// CTA tile 128x128, BK=64, 8 warps (2m x 4n), warp tile 64x32, 2 CTAs/SM.
// A loaded RAW (pimgb) via cp.async; relu(pretxt+pimgb) applied on FRAGMENTS
// after ldmatrix (pretxt is row-broadcast -> 2-reg fragment from SMEM copy).
// This removes the A-synthesis store pass + prefetch registers (spill fix).
// Dynamic SMEM 73728B:
//   A raw: [2][128][72] bf16 @ 0     (stage 18432B, row 144B)
//   B:     [2][64][136] bf16 @ 36864 (stage 17408B, row 272B)
//   pretxt row: 1024 bf16 @ 71680
// ============================================================================
#define LDSM_X4(r0,r1,r2,r3,addr) \
    asm volatile("ldmatrix.sync.aligned.m8n8.x4.shared.b16 {%0,%1,%2,%3}, [%4];" \
        : "=r"(r0),"=r"(r1),"=r"(r2),"=r"(r3) : "r"(addr))
#define LDSM_X4_T(r0,r1,r2,r3,addr) \
    asm volatile("ldmatrix.sync.aligned.m8n8.x4.trans.shared.b16 {%0,%1,%2,%3}, [%4];" \
        : "=r"(r0),"=r"(r1),"=r"(r2),"=r"(r3) : "r"(addr))
#define MMA_BF16(d0,d1,d2,d3,a0,a1,a2,a3,b0,b1) \
    asm volatile("mma.sync.aligned.m16n8k16.row.col.f32.bf16.bf16.f32 " \
        "{%0,%1,%2,%3}, {%4,%5,%6,%7}, {%8,%9}, {%0,%1,%2,%3};" \
        : "+f"(d0),"+f"(d1),"+f"(d2),"+f"(d3) \
        : "r"(a0),"r"(a1),"r"(a2),"r"(a3),"r"(b0),"r"(b1))

#define BIG_SMEM 73728

// relu(raw + pt) on one bf16x2 word
__device__ __forceinline__ uint32_t fuse1(uint32_t raw, uint32_t pt)
{
    const __nv_bfloat162 z = __float2bfloat162_rn(0.0f);
    __nv_bfloat162 v = __hmax2(__hadd2(*(__nv_bfloat162*)&raw,
                                       *(__nv_bfloat162*)&pt), z);
    return *(uint32_t*)&v;
}

__global__ void __launch_bounds__(256, 2)
big_gemm_mma(const __nv_bfloat16* __restrict__ pretxt,
             const __nv_bfloat16* __restrict__ pimgb,
             const __nv_bfloat16* __restrict__ rw2,
             const float* __restrict__ image,
             const float* __restrict__ rb2,
             float* __restrict__ out)
{
    extern __shared__ char smem[];
    __nv_bfloat16* As0  = (__nv_bfloat16*)smem;              // [2][128][72] raw pimgb
    __nv_bfloat16* Bs0  = (__nv_bfloat16*)(smem + 36864);    // [2][64][136]
    uint32_t*      ptx2 = (uint32_t*)(smem + 71680);         // pretxt row as bf16x2[512]

    const uint32_t ASTG = 18432;   // bytes per A stage
    const uint32_t BSTG = 17408;   // bytes per B stage

    const int t    = threadIdx.x;
    const int lane = t & 31;
    const int warp = t >> 5;
    const int n0 = blockIdx.x * 128;
    const int m0 = blockIdx.y * 128;
    const int i  = m0 >> 8;
    const int j0 = m0 & 255;

    const int wm = (warp >> 2) * 64;   // 0 or 64
    const int wn = (warp & 3) * 32;    // 0..96

    // loaders (per chunk of 64 k)
    const int ar  = t >> 1;            // A row 0..127
    const int akv = (t & 1) * 32;      // elem offset 0 or 32
    const int br  = t >> 2;            // B k row 0..63
    const int bnv = (t & 3) * 32;      // elem offset 0..96

    const __nv_bfloat16* ptrow = pretxt + (size_t)i * DD;
    const __nv_bfloat16* parow = pimgb + (size_t)(j0 + ar) * DD + akv;
    const __nv_bfloat16* pbrow = rw2 + (size_t)br * DD + n0 + bnv;

    const uint32_t adst0 = (uint32_t)__cvta_generic_to_shared(
        As0 + ar * 72 + akv);
    const uint32_t bdst0 = (uint32_t)__cvta_generic_to_shared(
        Bs0 + br * 136 + bnv);

    const uint32_t aBase = (uint32_t)__cvta_generic_to_shared(As0)
        + (wm + ((lane >> 3) & 1) * 8 + (lane & 7)) * 144 + (lane >> 4) * 16;
    const uint32_t bBase = (uint32_t)__cvta_generic_to_shared(Bs0)
        + (((lane >> 3) & 1) * 8 + (lane & 7)) * 272 + (wn + (lane >> 4) * 8) * 2;

    float acc[4][4][4] = {};   // [mt][nt][reg]

    // --- prologue ---
    // stage full pretxt row into SMEM (4 bf16 per thread)
    *(uint2*)((__nv_bfloat16*)ptx2 + t * 4) = *(const uint2*)(ptrow + t * 4);
    // chunk 0: A raw + B via cp.async
    #pragma unroll
    for (int q = 0; q < 4; q++) {
        CP_ASYNC16(adst0 + q * 16, parow + q * 8);
        CP_ASYNC16(bdst0 + q * 16, pbrow + q * 8);
    }
    CP_COMMIT();
    CP_WAIT0();
    __syncthreads();

    const int lk = lane & 3;   // pretxt fragment word offset

    for (int c = 0; c < 16; c++) {
        const int s  = c & 1;
        const int ns = s ^ 1;
        const int kn = (c + 1) * 64;

        if (c < 15) {   // issue next-chunk loads; latency overlaps compute
            const __nv_bfloat16* asrc = parow + kn;
            const __nv_bfloat16* bsrc = pbrow + (size_t)kn * DD;
            #pragma unroll
            for (int q = 0; q < 4; q++) {
                CP_ASYNC16(adst0 + ns * ASTG + q * 16, asrc + q * 8);
                CP_ASYNC16(bdst0 + ns * BSTG + q * 16, bsrc + q * 8);
            }
            CP_COMMIT();
        }

        // ---- compute 4 k16 steps on stage s ----
        const uint32_t aB = aBase + s * ASTG;
        const uint32_t bB = bBase + s * BSTG;
        #pragma unroll
        for (int ks = 0; ks < 4; ks++) {
            const int kk = ks * 16;
            // pretxt fragment: regs 0,1 need k[0..7], regs 2,3 need k[8..15]
            const uint32_t ptA = ptx2[((c * 64 + kk) >> 1) + lk];
            const uint32_t ptB = ptx2[((c * 64 + kk) >> 1) + 4 + lk];
            unsigned a[4][4];
            #pragma unroll
            for (int mt = 0; mt < 4; mt++) {
                LDSM_X4(a[mt][0], a[mt][1], a[mt][2], a[mt][3],
                        aB + mt * 16 * 144 + kk * 2);
                a[mt][0] = fuse1(a[mt][0], ptA);
                a[mt][1] = fuse1(a[mt][1], ptA);
                a[mt][2] = fuse1(a[mt][2], ptB);
                a[mt][3] = fuse1(a[mt][3], ptB);
            }
            unsigned b[4][2];
            #pragma unroll
            for (int bt = 0; bt < 2; bt++)
                LDSM_X4_T(b[bt*2][0], b[bt*2][1], b[bt*2+1][0], b[bt*2+1][1],
                          bB + kk * 272 + bt * 32);
            #pragma unroll
            for (int mt = 0; mt < 4; mt++)
                #pragma unroll
                for (int nt = 0; nt < 4; nt++)
                    MMA_BF16(acc[mt][nt][0], acc[mt][nt][1],
                             acc[mt][nt][2], acc[mt][nt][3],
                             a[mt][0], a[mt][1], a[mt][2], a[mt][3],
                             b[nt][0], b[nt][1]);
        }

        if (c < 15) {
            CP_WAIT0();
            __syncthreads();
        }
    }

    // ---- epilogue: + image[j] + rb2 ----
    #pragma unroll
    for (int mt = 0; mt < 4; mt++) {
        const int rbase = wm + mt * 16 + (lane >> 2);
        #pragma unroll
        for (int half = 0; half < 2; half++) {
            const int r = rbase + half * 8;
            const float* img = image + (size_t)(j0 + r) * DD;
            const size_t orow = (size_t)(m0 + r) * DD;
            #pragma unroll
            for (int nt = 0; nt < 4; nt++) {
                const int col = n0 + wn + nt * 8 + (lane & 3) * 2;
                float2 im = *(const float2*)(img + col);
                float2 rb = *(const float2*)(rb2 + col);
                float2 o;
                o.x = acc[mt][nt][half * 2 + 0] + im.x + rb.x;
                o.y = acc[mt][nt][half * 2 + 1] + im.y + rb.y;
                *(float2*)(out + orow + col) = o;
            }
        }
    }
}

// ---------------------------------------------------------------------------
extern "C" void kernel_launch(void* const* d_in, const int* in_sizes, int n_in,
                              void* d_out, int out_size)
{
    const float* image = (const float*)d_in[0];
    const float* text  = (const float*)d_in[1];
    const float* aw1   = (const float*)d_in[2];
    const float* ab1   = (const float*)d_in[3];
    const float* aw2   = (const float*)d_in[4];
    const float* ab2   = (const float*)d_in[5];
    const float* rw1   = (const float*)d_in[6];
    const float* rb1   = (const float*)d_in[7];
    const float* rw2   = (const float*)d_in[8];
    const float* rb2   = (const float*)d_in[9];
    float* out = (float*)d_out;

    float *h_p, *logits_p, *text2_p;
    __nv_bfloat16 *pretxt_p, *pimgb_p, *rw2h_p;
    cudaGetSymbolAddress((void**)&h_p,      g_h);
    cudaGetSymbolAddress((void**)&logits_p, g_logits);
    cudaGetSymbolAddress((void**)&text2_p,  g_text2);
    cudaGetSymbolAddress((void**)&pretxt_p, g_pretxt_h);
    cudaGetSymbolAddress((void**)&pimgb_p,  g_pimgb_h);
    cudaGetSymbolAddress((void**)&rw2h_p,   g_rw2_h);

    // Host-side attr set; deterministic & idempotent.
    cudaFuncSetAttribute(big_gemm_mma,
                         cudaFuncAttributeMaxDynamicSharedMemorySize, BIG_SMEM);

    dim3 blk(256);

    // rw2 -> bf16 (independent of the chain)
    convert_rw2<<<DD * DD / 1024, blk>>>(rw2, rw2h_p);
    // z=0: h = relu(text@aw1+ab1); z=1: pimgb = bf16(image@rw1[:D]+rb1)
    small_pair<<<dim3(16, 4, 2), blk, SMALL_SMEM>>>(
        text, aw1, ab1, h_p, image, rw1, rb1, pimgb_p);
    // logits = h @ aw2 + ab2
    small_logits<<<dim3(16, 4), blk, SMALL_SMEM>>>(h_p, aw2, ab2, logits_p);
    // text2 = text * softmax(logits)
    softmax_mul<<<BSZ, blk>>>(logits_p, text, text2_p);
    // pretxt = bf16(text2 @ rw1[D:])
    small_pretxt<<<dim3(16, 4), blk, SMALL_SMEM>>>(
        text2_p, rw1 + (size_t)DD * DD, pretxt_p);
    // big fused GEMM on tensor cores (mma.sync), fragment-side A fusion
    big_gemm_mma<<<dim3(8, 512), blk, BIG_SMEM>>>(
        pretxt_p, pimgb_p, rw2h_p, image, rb2, out);
}

// round 8
// speedup vs baseline: 1.5999x; 1.5999x over previous
#include <cuda_runtime.h>
#include <cuda_fp16.h>
#include <math.h>
#include <stdint.h>

#define DD 1024
#define BSZ 256

// ---- scratch globals --------------------------------------------------------
__device__ float g_h[BSZ * DD];
__device__ float g_logits[BSZ * DD];
__device__ float g_text2[BSZ * DD];
__device__ __half g_pretxt_h[BSZ * DD];
__device__ __half g_pimgb_h[BSZ * DD];
__device__ __half g_rw2_h[DD * DD];   // rw2 fp16, [k][n]

// ---- cp.async helpers ------------------------------------------------------
#define CP_ASYNC16(dst, src) \
    asm volatile("cp.async.cg.shared.global [%0], [%1], 16;" \
        :: "r"(dst), "l"(src) : "memory")
#define CP_COMMIT() asm volatile("cp.async.commit_group;" ::: "memory")
#define CP_WAIT0()  asm volatile("cp.async.wait_group 0;" ::: "memory")

// ============================================================================
// Small-chain fp32 GEMMs (structure unchanged — known good):
// 64x64 tile, BK=32, double-buffered, register prefetch, one sync per chunk.
// ============================================================================
template <bool RELU, bool HAS_BIAS, bool HALFOUT>
__device__ __forceinline__ void gemm64_body(
    const float* __restrict__ A, const float* __restrict__ B,
    const float* __restrict__ bias, void* __restrict__ Cv, float* smem)
{
    const int AS  = 32 * 68;
    const int BS_ = 32 * 64;
    const int STG = AS + BS_;

    const int t  = threadIdx.x;
    const int m0 = blockIdx.y * 64;
    const int n0 = blockIdx.x * 64;
    const int tx = t & 15, ty = t >> 4;

    const int ar  = t & 63;
    const int akv = (t >> 6) * 8;
    const int bk  = t >> 3;
    const int bnv = (t & 7) * 8;

    const float* Arow = A + (size_t)(m0 + ar) * DD + akv;
    const float* Brow = B + (size_t)bk * DD + n0 + bnv;

    float4 a0, a1, b0, b1;
    a0 = *(const float4*)(Arow);
    a1 = *(const float4*)(Arow + 4);
    b0 = *(const float4*)(Brow);
    b1 = *(const float4*)(Brow + 4);
    {
        float* Ad = smem;
        float* Bd = smem + AS;
        Ad[(akv + 0) * 68 + ar] = a0.x; Ad[(akv + 1) * 68 + ar] = a0.y;
        Ad[(akv + 2) * 68 + ar] = a0.z; Ad[(akv + 3) * 68 + ar] = a0.w;
        Ad[(akv + 4) * 68 + ar] = a1.x; Ad[(akv + 5) * 68 + ar] = a1.y;
        Ad[(akv + 6) * 68 + ar] = a1.z; Ad[(akv + 7) * 68 + ar] = a1.w;
        *(float4*)(&Bd[bk * 64 + bnv])     = b0;
        *(float4*)(&Bd[bk * 64 + bnv + 4]) = b1;
    }
    __syncthreads();

    float acc[4][4] = {};

    for (int c = 0; c < 32; c++) {
        const int s = c & 1;
        const float* As = smem + s * STG;
        const float* Bs = smem + s * STG + AS;
        const int kn = (c + 1) * 32;

        if (c < 31) {
            a0 = *(const float4*)(Arow + kn);
            a1 = *(const float4*)(Arow + kn + 4);
            b0 = *(const float4*)(Brow + (size_t)kn * DD);
            b1 = *(const float4*)(Brow + (size_t)kn * DD + 4);
        }

        #pragma unroll
        for (int kk = 0; kk < 32; kk++) {
            float a[4], b[4];
            *(float4*)a = *(const float4*)(&As[kk * 68 + ty * 4]);
            *(float4*)b = *(const float4*)(&Bs[kk * 64 + tx * 4]);
            #pragma unroll
            for (int r = 0; r < 4; r++)
                #pragma unroll
                for (int cc = 0; cc < 4; cc++)
                    acc[r][cc] = fmaf(a[r], b[cc], acc[r][cc]);
        }

        if (c < 31) {
            float* Ad = smem + (s ^ 1) * STG;
            float* Bd = Ad + AS;
            Ad[(akv + 0) * 68 + ar] = a0.x; Ad[(akv + 1) * 68 + ar] = a0.y;
            Ad[(akv + 2) * 68 + ar] = a0.z; Ad[(akv + 3) * 68 + ar] = a0.w;
            Ad[(akv + 4) * 68 + ar] = a1.x; Ad[(akv + 5) * 68 + ar] = a1.y;
            Ad[(akv + 6) * 68 + ar] = a1.z; Ad[(akv + 7) * 68 + ar] = a1.w;
            *(float4*)(&Bd[bk * 64 + bnv])     = b0;
            *(float4*)(&Bd[bk * 64 + bnv + 4]) = b1;
        }
        __syncthreads();
    }

    #pragma unroll
    for (int r = 0; r < 4; r++) {
        const int m = m0 + ty * 4 + r;
        #pragma unroll
        for (int c = 0; c < 4; c++) {
            const int n = n0 + tx * 4 + c;
            float v = acc[r][c];
            if (HAS_BIAS) v += bias[n];
            if (RELU) v = fmaxf(v, 0.0f);
            if (HALFOUT)
                ((__half*)Cv)[(size_t)m * DD + n] = __float2half(v);
            else
                ((float*)Cv)[(size_t)m * DD + n] = v;
        }
    }
}

#define SMALL_SMEM (2 * (32 * 68 + 32 * 64) * (int)sizeof(float))

__global__ void __launch_bounds__(256)
small_pair(const float* __restrict__ text, const float* __restrict__ aw1,
           const float* __restrict__ ab1, float* __restrict__ h,
           const float* __restrict__ image, const float* __restrict__ rw1,
           const float* __restrict__ rb1, __half* __restrict__ pimgb)
{
    extern __shared__ float smemf[];
    if (blockIdx.z == 0)
        gemm64_body<true, true, false>(text, aw1, ab1, h, smemf);
    else
        gemm64_body<false, true, true>(image, rw1, rb1, pimgb, smemf);
}

__global__ void __launch_bounds__(256)
small_logits(const float* __restrict__ h, const float* __restrict__ aw2,
             const float* __restrict__ ab2, float* __restrict__ logits)
{
    extern __shared__ float smemf[];
    gemm64_body<false, true, false>(h, aw2, ab2, logits, smemf);
}

__global__ void __launch_bounds__(256)
small_pretxt(const float* __restrict__ text2, const float* __restrict__ rw1b,
             __half* __restrict__ pretxt)
{
    extern __shared__ float smemf[];
    gemm64_body<false, false, true>(text2, rw1b, nullptr, pretxt, smemf);
}

// ---------------------------------------------------------------------------
__global__ void __launch_bounds__(256)
convert_rw2(const float* __restrict__ in, __half* __restrict__ out)
{
    const int idx = (blockIdx.x * 256 + threadIdx.x) * 4;
    float4 v = *(const float4*)(in + idx);
    __half o[4] = {
        __float2half(v.x), __float2half(v.y),
        __float2half(v.z), __float2half(v.w)};
    *(uint2*)(out + idx) = *(uint2*)o;
}

// ---------------------------------------------------------------------------
__global__ void __launch_bounds__(256)
softmax_mul(const float* __restrict__ logits, const float* __restrict__ text,
            float* __restrict__ out)
{
    const int row = blockIdx.x;
    const int t   = threadIdx.x;
    const float* l = logits + (size_t)row * DD;
    __shared__ float smax[8];
    __shared__ float ssum[8];

    float m = -1e30f;
    #pragma unroll
    for (int k = t; k < DD; k += 256) m = fmaxf(m, l[k]);
    #pragma unroll
    for (int o = 16; o > 0; o >>= 1)
        m = fmaxf(m, __shfl_xor_sync(0xffffffffu, m, o));
    if ((t & 31) == 0) smax[t >> 5] = m;
    __syncthreads();
    float rowmax = smax[0];
    #pragma unroll
    for (int w = 1; w < 8; w++) rowmax = fmaxf(rowmax, smax[w]);

    float s = 0.0f;
    #pragma unroll
    for (int k = t; k < DD; k += 256) s += expf(l[k] - rowmax);
    #pragma unroll
    for (int o = 16; o > 0; o >>= 1)
        s += __shfl_xor_sync(0xffffffffu, s, o);
    if ((t & 31) == 0) ssum[t >> 5] = s;
    __syncthreads();
    float tot = 0.0f;
    #pragma unroll
    for (int w = 0; w < 8; w++) tot += ssum[w];
    const float inv = 1.0f / tot;

    const float* tr = text + (size_t)row * DD;
    float* orow = out + (size_t)row * DD;
    #pragma unroll
    for (int k = t; k < DD; k += 256)
        orow[k] = tr[k] * (expf(l[k] - rowmax) * inv);
}

// ============================================================================
// Big GEMM on mma.sync fp16 with fp16 ACCUMULATION (2x rate hypothesis).
// CTA tile 128x128, BK=32, 512 threads = 16 warps (4m x 4n), warp tile 32x32.
// fp16 acc per 128-K segment, promoted to fp32 registers every 4 chunks.
// SMEM-side relu(pretxt+pimgb) fusion (round-4 style). 1 CTA/SM (16 warps).
// Static SMEM < 48KB:
//   A: [2][128][40] fp16 (row 80B), B: [2][32][136] fp16 (row 272B), ptxs[1024]
// ============================================================================
#define LDSM_X4(r0,r1,r2,r3,addr) \
    asm volatile("ldmatrix.sync.aligned.m8n8.x4.shared.b16 {%0,%1,%2,%3}, [%4];" \
        : "=r"(r0),"=r"(r1),"=r"(r2),"=r"(r3) : "r"(addr))
#define LDSM_X4_T(r0,r1,r2,r3,addr) \
    asm volatile("ldmatrix.sync.aligned.m8n8.x4.trans.shared.b16 {%0,%1,%2,%3}, [%4];" \
        : "=r"(r0),"=r"(r1),"=r"(r2),"=r"(r3) : "r"(addr))
// fp16 accumulate: D,C are 2 b32 regs (f16x2 pairs)
#define MMA_F16ACC(d0,d1,a0,a1,a2,a3,b0,b1) \
    asm volatile("mma.sync.aligned.m16n8k16.row.col.f16.f16.f16.f16 " \
        "{%0,%1}, {%2,%3,%4,%5}, {%6,%7}, {%0,%1};" \
        : "+r"(d0),"+r"(d1) \
        : "r"(a0),"r"(a1),"r"(a2),"r"(a3),"r"(b0),"r"(b1))

__device__ __forceinline__ uint4 fuse_relu_f16(uint4 p, uint4 t)
{
    const __half2 z = __float2half2_rn(0.0f);
    uint4 r;
    const __half2* pp = (const __half2*)&p;
    const __half2* tt = (const __half2*)&t;
    __half2* rr = (__half2*)&r;
    #pragma unroll
    for (int q = 0; q < 4; q++)
        rr[q] = __hmax2(__hadd2(pp[q], tt[q]), z);
    return r;
}

__global__ void __launch_bounds__(512, 1)
big_gemm_mma(const __half* __restrict__ pretxt,
             const __half* __restrict__ pimgb,
             const __half* __restrict__ rw2,
             const float* __restrict__ image,
             const float* __restrict__ rb2,
             float* __restrict__ out)
{
    __shared__ __half As[2][128][40];    // 20480B
    __shared__ __half Bs[2][32][136];    // 17408B
    __shared__ __half ptxs[1024];        // 2048B

    const uint32_t ASTG = 128 * 40 * 2;  // 10240
    const uint32_t BSTG = 32 * 136 * 2;  // 8704

    const int t    = threadIdx.x;
    const int lane = t & 31;
    const int warp = t >> 5;             // 0..15
    const int n0 = blockIdx.x * 128;
    const int m0 = blockIdx.y * 128;
    const int i  = m0 >> 8;
    const int j0 = m0 & 255;

    const int wm = (warp >> 2) * 32;     // 0,32,64,96
    const int wn = (warp & 3) * 32;      // 0,32,64,96

    // loaders (chunk = 128x32 A, 32x128 B; one uint4 / cp.async16 per thread)
    const int ar  = t >> 2;              // A row 0..127
    const int akv = (t & 3) * 8;         // A col 0,8,16,24
    const int br  = t >> 4;              // B k row 0..31
    const int bnv = (t & 15) * 8;        // B col 0..120

    const __half* ptrow = pretxt + (size_t)i * DD;
    const __half* parow = pimgb + (size_t)(j0 + ar) * DD + akv;
    const __half* pbrow = rw2 + (size_t)br * DD + n0 + bnv;

    const uint32_t bdst0 = (uint32_t)__cvta_generic_to_shared(&Bs[0][br][bnv]);

    const uint32_t aBase = (uint32_t)__cvta_generic_to_shared(
        &As[0][wm + ((lane >> 3) & 1) * 8 + (lane & 7)][(lane >> 4) * 8]);
    const uint32_t bBase = (uint32_t)__cvta_generic_to_shared(
        &Bs[0][((lane >> 3) & 1) * 8 + (lane & 7)][wn + (lane >> 4) * 8]);

    float    acc32[2][4][4] = {};        // [mt][nt][reg] fp32 running sum
    uint32_t acc16[2][4][2] = {};        // [mt][nt][reg] fp16x2 segment acc

    // --- prologue ---
    // stage pretxt row into SMEM (2 fp16 per thread)
    *(uint32_t*)(ptxs + t * 2) = *(const uint32_t*)(ptrow + t * 2);
    // chunk 0: B via cp.async, A fused (pretxt from global this once)
    CP_ASYNC16(bdst0, pbrow);
    CP_COMMIT();
    {
        uint4 pv = *(const uint4*)(parow);
        uint4 tv = *(const uint4*)(ptrow + akv);
        *(uint4*)(&As[0][ar][akv]) = fuse_relu_f16(pv, tv);
    }
    CP_WAIT0();
    __syncthreads();

    uint4 pv;
    for (int c = 0; c < 32; c++) {
        const int s  = c & 1;
        const int ns = s ^ 1;
        const int kn = (c + 1) * 32;

        if (c < 31) {   // issue next-chunk loads; latency overlaps compute
            CP_ASYNC16(bdst0 + ns * BSTG, pbrow + (size_t)kn * DD);
            CP_COMMIT();
            pv = *(const uint4*)(parow + kn);
        }

        // ---- compute 2 k16 steps on stage s (fp16 accumulate) ----
        const uint32_t aB = aBase + s * ASTG;
        const uint32_t bB = bBase + s * BSTG;
        #pragma unroll
        for (int ks = 0; ks < 2; ks++) {
            const int kk = ks * 16;
            unsigned a[2][4];
            #pragma unroll
            for (int mt = 0; mt < 2; mt++)
                LDSM_X4(a[mt][0], a[mt][1], a[mt][2], a[mt][3],
                        aB + mt * 16 * 80 + kk * 2);
            unsigned b[4][2];
            #pragma unroll
            for (int bt = 0; bt < 2; bt++)
                LDSM_X4_T(b[bt*2][0], b[bt*2][1], b[bt*2+1][0], b[bt*2+1][1],
                          bB + kk * 272 + bt * 32);
            #pragma unroll
            for (int mt = 0; mt < 2; mt++)
                #pragma unroll
                for (int nt = 0; nt < 4; nt++)
                    MMA_F16ACC(acc16[mt][nt][0], acc16[mt][nt][1],
                               a[mt][0], a[mt][1], a[mt][2], a[mt][3],
                               b[nt][0], b[nt][1]);
        }

        // ---- promote fp16 segment acc into fp32 every 4 chunks (128 K) ----
        if ((c & 3) == 3) {
            #pragma unroll
            for (int mt = 0; mt < 2; mt++)
                #pragma unroll
                for (int nt = 0; nt < 4; nt++) {
                    float2 f0 = __half22float2(*(__half2*)&acc16[mt][nt][0]);
                    float2 f1 = __half22float2(*(__half2*)&acc16[mt][nt][1]);
                    acc32[mt][nt][0] += f0.x;
                    acc32[mt][nt][1] += f0.y;
                    acc32[mt][nt][2] += f1.x;
                    acc32[mt][nt][3] += f1.y;
                    acc16[mt][nt][0] = 0;
                    acc16[mt][nt][1] = 0;
                }
        }

        if (c < 31) {   // fused A store into next stage (pretxt from SMEM)
            uint4 tv = *(const uint4*)(ptxs + kn + akv);
            *(uint4*)(&As[ns][ar][akv]) = fuse_relu_f16(pv, tv);
            CP_WAIT0();
        }
        __syncthreads();
    }

    // ---- epilogue: + image[j] + rb2 ----
    #pragma unroll
    for (int mt = 0; mt < 2; mt++) {
        const int rbase = wm + mt * 16 + (lane >> 2);
        #pragma unroll
        for (int half = 0; half < 2; half++) {
            const int r = rbase + half * 8;
            const float* img = image + (size_t)(j0 + r) * DD;
            const size_t orow = (size_t)(m0 + r) * DD;
            #pragma unroll
            for (int nt = 0; nt < 4; nt++) {
                const int col = n0 + wn + nt * 8 + (lane & 3) * 2;
                float2 im = *(const float2*)(img + col);
                float2 rb = *(const float2*)(rb2 + col);
                float2 o;
                o.x = acc32[mt][nt][half * 2 + 0] + im.x + rb.x;
                o.y = acc32[mt][nt][half * 2 + 1] + im.y + rb.y;
                *(float2*)(out + orow + col) = o;
            }
        }
    }
}

// ---------------------------------------------------------------------------
extern "C" void kernel_launch(void* const* d_in, const int* in_sizes, int n_in,
                              void* d_out, int out_size)
{
    const float* image = (const float*)d_in[0];
    const float* text  = (const float*)d_in[1];
    const float* aw1   = (const float*)d_in[2];
    const float* ab1   = (const float*)d_in[3];
    const float* aw2   = (const float*)d_in[4];
    const float* ab2   = (const float*)d_in[5];
    const float* rw1   = (const float*)d_in[6];
    const float* rb1   = (const float*)d_in[7];
    const float* rw2   = (const float*)d_in[8];
    const float* rb2   = (const float*)d_in[9];
    float* out = (float*)d_out;

    float *h_p, *logits_p, *text2_p;
    __half *pretxt_p, *pimgb_p, *rw2h_p;
    cudaGetSymbolAddress((void**)&h_p,      g_h);
    cudaGetSymbolAddress((void**)&logits_p, g_logits);
    cudaGetSymbolAddress((void**)&text2_p,  g_text2);
    cudaGetSymbolAddress((void**)&pretxt_p, g_pretxt_h);
    cudaGetSymbolAddress((void**)&pimgb_p,  g_pimgb_h);
    cudaGetSymbolAddress((void**)&rw2h_p,   g_rw2_h);

    dim3 blk(256);

    // rw2 -> fp16 (independent of the chain)
    convert_rw2<<<DD * DD / 1024, blk>>>(rw2, rw2h_p);
    // z=0: h = relu(text@aw1+ab1); z=1: pimgb = fp16(image@rw1[:D]+rb1)
    small_pair<<<dim3(16, 4, 2), blk, SMALL_SMEM>>>(
        text, aw1, ab1, h_p, image, rw1, rb1, pimgb_p);
    // logits = h @ aw2 + ab2
    small_logits<<<dim3(16, 4), blk, SMALL_SMEM>>>(h_p, aw2, ab2, logits_p);
    // text2 = text * softmax(logits)
    softmax_mul<<<BSZ, blk>>>(logits_p, text, text2_p);
    // pretxt = fp16(text2 @ rw1[D:])
    small_pretxt<<<dim3(16, 4), blk, SMALL_SMEM>>>(
        text2_p, rw1 + (size_t)DD * DD, pretxt_p);
    // big fused GEMM: fp16 mma.sync with fp16 accumulation (segmented)
    big_gemm_mma<<<dim3(8, 512), 512>>>(
        pretxt_p, pimgb_p, rw2h_p, image, rb2, out);
}

// round 9
// speedup vs baseline: 2.0017x; 1.2512x over previous
#include <cuda_runtime.h>
#include <cuda_fp16.h>
#include <math.h>
#include <stdint.h>

#define DD 1024
#define BSZ 256

// ---- scratch globals --------------------------------------------------------
__device__ __half g_h16[BSZ * DD];
__device__ float  g_logits[BSZ * DD];
__device__ __half g_text2_h[BSZ * DD];
__device__ __half g_pretxt_h[BSZ * DD];
__device__ __half g_pimgb_h[BSZ * DD];
__device__ __half g_rw2_h[DD * DD];   // rw2 fp16, [k][n]

// ---- cp.async helpers ------------------------------------------------------
#define CP_ASYNC16(dst, src) \
    asm volatile("cp.async.cg.shared.global [%0], [%1], 16;" \
        :: "r"(dst), "l"(src) : "memory")
#define CP_COMMIT() asm volatile("cp.async.commit_group;" ::: "memory")
#define CP_WAIT0()  asm volatile("cp.async.wait_group 0;" ::: "memory")

// ---- mma.sync / ldmatrix ----------------------------------------------------
#define LDSM_X4(r0,r1,r2,r3,addr) \
    asm volatile("ldmatrix.sync.aligned.m8n8.x4.shared.b16 {%0,%1,%2,%3}, [%4];" \
        : "=r"(r0),"=r"(r1),"=r"(r2),"=r"(r3) : "r"(addr))
#define LDSM_X4_T(r0,r1,r2,r3,addr) \
    asm volatile("ldmatrix.sync.aligned.m8n8.x4.trans.shared.b16 {%0,%1,%2,%3}, [%4];" \
        : "=r"(r0),"=r"(r1),"=r"(r2),"=r"(r3) : "r"(addr))
#define MMA_F16F32(d0,d1,d2,d3,a0,a1,a2,a3,b0,b1) \
    asm volatile("mma.sync.aligned.m16n8k16.row.col.f32.f16.f16.f32 " \
        "{%0,%1,%2,%3}, {%4,%5,%6,%7}, {%8,%9}, {%0,%1,%2,%3};" \
        : "+f"(d0),"+f"(d1),"+f"(d2),"+f"(d3) \
        : "r"(a0),"r"(a1),"r"(a2),"r"(a3),"r"(b0),"r"(b1))

// pack 8 fp32 -> 8 fp16 (uint4)
__device__ __forceinline__ uint4 pack8(const float4 x, const float4 y)
{
    __half2 h0 = __floats2half2_rn(x.x, x.y);
    __half2 h1 = __floats2half2_rn(x.z, x.w);
    __half2 h2 = __floats2half2_rn(y.x, y.y);
    __half2 h3 = __floats2half2_rn(y.z, y.w);
    uint4 r;
    r.x = *(uint32_t*)&h0; r.y = *(uint32_t*)&h1;
    r.z = *(uint32_t*)&h2; r.w = *(uint32_t*)&h3;
    return r;
}

// ============================================================================
// Small-chain GEMMs on fp16 mma.sync (f32 accum).
// C[256 x 1024] = A[256 x 1024] @ B[1024 x 1024] (+bias)(relu)
// CTA tile 64x64, BK=32, 128 threads = 4 warps (2m x 2n), warp tile 32x32.
// fp32 operands are converted to fp16 in the SMEM loader (no prepass).
// Double-buffered, register prefetch, one __syncthreads per chunk.
// ============================================================================
template <bool A16, bool RELU, bool HAS_BIAS, bool HALFOUT>
__device__ __forceinline__ void hgemm64_body(
    const void* __restrict__ Aptr, const float* __restrict__ B,
    const float* __restrict__ bias, void* __restrict__ Cv)
{
    __shared__ __half As[2][64][40];   // [m][k], row 80B
    __shared__ __half Bs[2][32][72];   // [k][n], row 144B

    const uint32_t ASTG = 64 * 40 * 2;   // 5120B
    const uint32_t BSTG = 32 * 72 * 2;   // 4608B

    const int t    = threadIdx.x;
    const int lane = t & 31;
    const int warp = t >> 5;             // 0..3
    const int m0 = blockIdx.y * 64;
    const int n0 = blockIdx.x * 64;

    const int wm = (warp >> 1) * 32;     // 0 or 32
    const int wn = (warp & 1) * 32;      // 0 or 32

    // loaders: A 64x32 (row=t>>1, kv=(t&1)*16); B 32x64 (kr=t>>2, nv=(t&3)*16)
    const int ar  = t >> 1;
    const int akv = (t & 1) * 16;
    const int bkr = t >> 2;
    const int bnv = (t & 3) * 16;

    const float* Af = (const float*)Aptr + (size_t)(m0 + ar) * DD + akv;
    const __half* Ah = (const __half*)Aptr + (size_t)(m0 + ar) * DD + akv;
    const float* Brow = B + (size_t)bkr * DD + n0 + bnv;

    const uint32_t aBase = (uint32_t)__cvta_generic_to_shared(
        &As[0][wm + ((lane >> 3) & 1) * 8 + (lane & 7)][(lane >> 4) * 8]);
    const uint32_t bBase = (uint32_t)__cvta_generic_to_shared(
        &Bs[0][((lane >> 3) & 1) * 8 + (lane & 7)][wn + (lane >> 4) * 8]);

    float acc[2][4][4] = {};

    // prefetch registers
    float4 af[4]; uint4 ah[2];
    float4 bf[4];

    // ---- prologue: chunk 0 ----
    if (A16) {
        ah[0] = *(const uint4*)(Ah);
        ah[1] = *(const uint4*)(Ah + 8);
    } else {
        af[0] = *(const float4*)(Af);
        af[1] = *(const float4*)(Af + 4);
        af[2] = *(const float4*)(Af + 8);
        af[3] = *(const float4*)(Af + 12);
    }
    bf[0] = *(const float4*)(Brow);
    bf[1] = *(const float4*)(Brow + 4);
    bf[2] = *(const float4*)(Brow + 8);
    bf[3] = *(const float4*)(Brow + 12);
    {
        if (A16) {
            *(uint4*)(&As[0][ar][akv])     = ah[0];
            *(uint4*)(&As[0][ar][akv + 8]) = ah[1];
        } else {
            *(uint4*)(&As[0][ar][akv])     = pack8(af[0], af[1]);
            *(uint4*)(&As[0][ar][akv + 8]) = pack8(af[2], af[3]);
        }
        *(uint4*)(&Bs[0][bkr][bnv])     = pack8(bf[0], bf[1]);
        *(uint4*)(&Bs[0][bkr][bnv + 8]) = pack8(bf[2], bf[3]);
    }
    __syncthreads();

    for (int c = 0; c < 32; c++) {
        const int s  = c & 1;
        const int ns = s ^ 1;
        const int kn = (c + 1) * 32;

        if (c < 31) {   // prefetch next chunk into registers
            if (A16) {
                ah[0] = *(const uint4*)(Ah + kn);
                ah[1] = *(const uint4*)(Ah + kn + 8);
            } else {
                af[0] = *(const float4*)(Af + kn);
                af[1] = *(const float4*)(Af + kn + 4);
                af[2] = *(const float4*)(Af + kn + 8);
                af[3] = *(const float4*)(Af + kn + 12);
            }
            bf[0] = *(const float4*)(Brow + (size_t)kn * DD);
            bf[1] = *(const float4*)(Brow + (size_t)kn * DD + 4);
            bf[2] = *(const float4*)(Brow + (size_t)kn * DD + 8);
            bf[3] = *(const float4*)(Brow + (size_t)kn * DD + 12);
        }

        // ---- compute 2 k16 steps on stage s ----
        const uint32_t aB = aBase + s * ASTG;
        const uint32_t bB = bBase + s * BSTG;
        #pragma unroll
        for (int ks = 0; ks < 2; ks++) {
            const int kk = ks * 16;
            unsigned a[2][4];
            #pragma unroll
            for (int mt = 0; mt < 2; mt++)
                LDSM_X4(a[mt][0], a[mt][1], a[mt][2], a[mt][3],
                        aB + mt * 16 * 80 + kk * 2);
            unsigned b[4][2];
            #pragma unroll
            for (int bt = 0; bt < 2; bt++)
                LDSM_X4_T(b[bt*2][0], b[bt*2][1], b[bt*2+1][0], b[bt*2+1][1],
                          bB + kk * 144 + bt * 32);
            #pragma unroll
            for (int mt = 0; mt < 2; mt++)
                #pragma unroll
                for (int nt = 0; nt < 4; nt++)
                    MMA_F16F32(acc[mt][nt][0], acc[mt][nt][1],
                               acc[mt][nt][2], acc[mt][nt][3],
                               a[mt][0], a[mt][1], a[mt][2], a[mt][3],
                               b[nt][0], b[nt][1]);
        }

        if (c < 31) {   // store prefetched chunk into next stage
            if (A16) {
                *(uint4*)(&As[ns][ar][akv])     = ah[0];
                *(uint4*)(&As[ns][ar][akv + 8]) = ah[1];
            } else {
                *(uint4*)(&As[ns][ar][akv])     = pack8(af[0], af[1]);
                *(uint4*)(&As[ns][ar][akv + 8]) = pack8(af[2], af[3]);
            }
            *(uint4*)(&Bs[ns][bkr][bnv])     = pack8(bf[0], bf[1]);
            *(uint4*)(&Bs[ns][bkr][bnv + 8]) = pack8(bf[2], bf[3]);
        }
        __syncthreads();
    }

    // ---- epilogue ----
    #pragma unroll
    for (int mt = 0; mt < 2; mt++) {
        const int rbase = wm + mt * 16 + (lane >> 2);
        #pragma unroll
        for (int half = 0; half < 2; half++) {
            const int r = m0 + rbase + half * 8;
            #pragma unroll
            for (int nt = 0; nt < 4; nt++) {
                const int col = n0 + wn + nt * 8 + (lane & 3) * 2;
                float v0 = acc[mt][nt][half * 2 + 0];
                float v1 = acc[mt][nt][half * 2 + 1];
                if (HAS_BIAS) { v0 += bias[col]; v1 += bias[col + 1]; }
                if (RELU) { v0 = fmaxf(v0, 0.0f); v1 = fmaxf(v1, 0.0f); }
                if (HALFOUT) {
                    __half2 h = __floats2half2_rn(v0, v1);
                    *(uint32_t*)((__half*)Cv + (size_t)r * DD + col) =
                        *(uint32_t*)&h;
                } else {
                    float2 f = make_float2(v0, v1);
                    *(float2*)((float*)Cv + (size_t)r * DD + col) = f;
                }
            }
        }
    }
}

// z=0: h16 = fp16(relu(text@aw1+ab1));  z=1: pimgb = fp16(image@rw1[:D]+rb1)
__global__ void __launch_bounds__(128)
small_pair(const float* __restrict__ text, const float* __restrict__ aw1,
           const float* __restrict__ ab1, __half* __restrict__ h16,
           const float* __restrict__ image, const float* __restrict__ rw1,
           const float* __restrict__ rb1, __half* __restrict__ pimgb)
{
    if (blockIdx.z == 0)
        hgemm64_body<false, true, true, true>(text, aw1, ab1, h16);
    else
        hgemm64_body<false, false, true, true>(image, rw1, rb1, pimgb);
}

__global__ void __launch_bounds__(128)
small_logits(const __half* __restrict__ h16, const float* __restrict__ aw2,
             const float* __restrict__ ab2, float* __restrict__ logits)
{
    hgemm64_body<true, false, true, false>(h16, aw2, ab2, logits);
}

__global__ void __launch_bounds__(128)
small_pretxt(const __half* __restrict__ text2, const float* __restrict__ rw1b,
             __half* __restrict__ pretxt)
{
    hgemm64_body<true, false, false, true>(text2, rw1b, nullptr, pretxt);
}

// ---------------------------------------------------------------------------
__global__ void __launch_bounds__(256)
convert_rw2(const float* __restrict__ in, __half* __restrict__ out)
{
    const int idx = (blockIdx.x * 256 + threadIdx.x) * 4;
    float4 v = *(const float4*)(in + idx);
    __half2 h0 = __floats2half2_rn(v.x, v.y);
    __half2 h1 = __floats2half2_rn(v.z, v.w);
    uint2 o; o.x = *(uint32_t*)&h0; o.y = *(uint32_t*)&h1;
    *(uint2*)(out + idx) = o;
}

// ---------------------------------------------------------------------------
// text2 = fp16(text * softmax(logits, axis=1))
__global__ void __launch_bounds__(256)
softmax_mul(const float* __restrict__ logits, const float* __restrict__ text,
            __half* __restrict__ out)
{
    const int row = blockIdx.x;
    const int t   = threadIdx.x;
    const float* l = logits + (size_t)row * DD;
    __shared__ float smax[8];
    __shared__ float ssum[8];

    float m = -1e30f;
    #pragma unroll
    for (int k = t; k < DD; k += 256) m = fmaxf(m, l[k]);
    #pragma unroll
    for (int o = 16; o > 0; o >>= 1)
        m = fmaxf(m, __shfl_xor_sync(0xffffffffu, m, o));
    if ((t & 31) == 0) smax[t >> 5] = m;
    __syncthreads();
    float rowmax = smax[0];
    #pragma unroll
    for (int w = 1; w < 8; w++) rowmax = fmaxf(rowmax, smax[w]);

    float s = 0.0f;
    #pragma unroll
    for (int k = t; k < DD; k += 256) s += expf(l[k] - rowmax);
    #pragma unroll
    for (int o = 16; o > 0; o >>= 1)
        s += __shfl_xor_sync(0xffffffffu, s, o);
    if ((t & 31) == 0) ssum[t >> 5] = s;
    __syncthreads();
    float tot = 0.0f;
    #pragma unroll
    for (int w = 0; w < 8; w++) tot += ssum[w];
    const float inv = 1.0f / tot;

    const float* tr = text + (size_t)row * DD;
    __half* orow = out + (size_t)row * DD;
    #pragma unroll
    for (int k = t * 2; k < DD; k += 512) {
        float w0 = tr[k]     * (expf(l[k]     - rowmax) * inv);
        float w1 = tr[k + 1] * (expf(l[k + 1] - rowmax) * inv);
        __half2 h = __floats2half2_rn(w0, w1);
        *(uint32_t*)(orow + k) = *(uint32_t*)&h;
    }
}

// ============================================================================
// Big GEMM on mma.sync (fp16 in, fp32 accum) — round-4 structure (at the
// register-MMA issue floor): CTA 128x128, BK=32, 8 warps (2m x 4n),
// warp tile 64x32, 2 CTAs/SM, double-buffered, cp.async for B,
// SMEM-side relu(pretxt+pimgb) A synthesis.
// ============================================================================
__device__ __forceinline__ uint4 fuse_relu_f16(uint4 p, uint4 t)
{
    const __half2 z = __float2half2_rn(0.0f);
    uint4 r;
    const __half2* pp = (const __half2*)&p;
    const __half2* tt = (const __half2*)&t;
    __half2* rr = (__half2*)&r;
    #pragma unroll
    for (int q = 0; q < 4; q++)
        rr[q] = __hmax2(__hadd2(pp[q], tt[q]), z);
    return r;
}

__global__ void __launch_bounds__(256, 2)
big_gemm_mma(const __half* __restrict__ pretxt,
             const __half* __restrict__ pimgb,
             const __half* __restrict__ rw2,
             const float* __restrict__ image,
             const float* __restrict__ rb2,
             float* __restrict__ out)
{
    __shared__ __half As[2][128][40];   // [m][k], 80B rows
    __shared__ __half Bs[2][32][136];   // [k][n], 272B rows

    const uint32_t ASTG = 128 * 40 * 2;
    const uint32_t BSTG = 32 * 136 * 2;

    const int t    = threadIdx.x;
    const int lane = t & 31;
    const int warp = t >> 5;
    const int n0 = blockIdx.x * 128;
    const int m0 = blockIdx.y * 128;
    const int i  = m0 >> 8;
    const int j0 = m0 & 255;

    const int wm = (warp >> 2) * 64;
    const int wn = (warp & 3) * 32;

    const int ar  = t >> 1;
    const int akv = (t & 1) * 16;
    const int br  = t >> 3;
    const int bnv = (t & 7) * 16;

    const __half* ptrow = pretxt + (size_t)i * DD;
    const __half* parow = pimgb + (size_t)(j0 + ar) * DD + akv;
    const __half* pbrow = rw2 + (size_t)br * DD + n0 + bnv;

    const uint32_t bdst0 = (uint32_t)__cvta_generic_to_shared(&Bs[0][br][bnv]);

    const uint32_t aBase = (uint32_t)__cvta_generic_to_shared(
        &As[0][wm + ((lane >> 3) & 1) * 8 + (lane & 7)][(lane >> 4) * 8]);
    const uint32_t bBase = (uint32_t)__cvta_generic_to_shared(
        &Bs[0][((lane >> 3) & 1) * 8 + (lane & 7)][wn + (lane >> 4) * 8]);

    float acc[4][4][4] = {};

    // --- prologue: chunk 0 into stage 0 ---
    CP_ASYNC16(bdst0,      pbrow);
    CP_ASYNC16(bdst0 + 16, pbrow + 8);
    CP_COMMIT();
    {
        uint4 pv0 = *(const uint4*)(parow);
        uint4 pv1 = *(const uint4*)(parow + 8);
        uint4 tv0 = *(const uint4*)(ptrow + akv);
        uint4 tv1 = *(const uint4*)(ptrow + akv + 8);
        *(uint4*)(&As[0][ar][akv])     = fuse_relu_f16(pv0, tv0);
        *(uint4*)(&As[0][ar][akv + 8]) = fuse_relu_f16(pv1, tv1);
    }
    CP_WAIT0();
    __syncthreads();

    uint4 pv0, pv1, tv0, tv1;
    for (int c = 0; c < 32; c++) {
        const int s  = c & 1;
        const int ns = s ^ 1;
        const int kn = (c + 1) * 32;

        if (c < 31) {
            CP_ASYNC16(bdst0 + ns * BSTG,      pbrow + (size_t)kn * DD);
            CP_ASYNC16(bdst0 + ns * BSTG + 16, pbrow + (size_t)kn * DD + 8);
            CP_COMMIT();
            pv0 = *(const uint4*)(parow + kn);
            pv1 = *(const uint4*)(parow + kn + 8);
            tv0 = *(const uint4*)(ptrow + kn + akv);
            tv1 = *(const uint4*)(ptrow + kn + akv + 8);
        }

        const uint32_t aB = aBase + s * ASTG;
        const uint32_t bB = bBase + s * BSTG;
        #pragma unroll
        for (int ks = 0; ks < 2; ks++) {
            const int kk = ks * 16;
            unsigned a[4][4];
            #pragma unroll
            for (int mt = 0; mt < 4; mt++)
                LDSM_X4(a[mt][0], a[mt][1], a[mt][2], a[mt][3],
                        aB + mt * 16 * 80 + kk * 2);
            unsigned b[4][2];
            #pragma unroll
            for (int bt = 0; bt < 2; bt++)
                LDSM_X4_T(b[bt*2][0], b[bt*2][1], b[bt*2+1][0], b[bt*2+1][1],
                          bB + kk * 272 + bt * 32);
            #pragma unroll
            for (int mt = 0; mt < 4; mt++)
                #pragma unroll
                for (int nt = 0; nt < 4; nt++)
                    MMA_F16F32(acc[mt][nt][0], acc[mt][nt][1],
                               acc[mt][nt][2], acc[mt][nt][3],
                               a[mt][0], a[mt][1], a[mt][2], a[mt][3],
                               b[nt][0], b[nt][1]);
        }

        if (c < 31) {
            *(uint4*)(&As[ns][ar][akv])     = fuse_relu_f16(pv0, tv0);
            *(uint4*)(&As[ns][ar][akv + 8]) = fuse_relu_f16(pv1, tv1);
            CP_WAIT0();
        }
        __syncthreads();
    }

    // ---- epilogue: + image[j] + rb2 ----
    #pragma unroll
    for (int mt = 0; mt < 4; mt++) {
        const int rbase = wm + mt * 16 + (lane >> 2);
        #pragma unroll
        for (int half = 0; half < 2; half++) {
            const int r = rbase + half * 8;
            const float* img = image + (size_t)(j0 + r) * DD;
            const size_t orow = (size_t)(m0 + r) * DD;
            #pragma unroll
            for (int nt = 0; nt < 4; nt++) {
                const int col = n0 + wn + nt * 8 + (lane & 3) * 2;
                float2 im = *(const float2*)(img + col);
                float2 rb = *(const float2*)(rb2 + col);
                float2 o;
                o.x = acc[mt][nt][half * 2 + 0] + im.x + rb.x;
                o.y = acc[mt][nt][half * 2 + 1] + im.y + rb.y;
                *(float2*)(out + orow + col) = o;
            }
        }
    }
}

// ---------------------------------------------------------------------------
extern "C" void kernel_launch(void* const* d_in, const int* in_sizes, int n_in,
                              void* d_out, int out_size)
{
    const float* image = (const float*)d_in[0];
    const float* text  = (const float*)d_in[1];
    const float* aw1   = (const float*)d_in[2];
    const float* ab1   = (const float*)d_in[3];
    const float* aw2   = (const float*)d_in[4];
    const float* ab2   = (const float*)d_in[5];
    const float* rw1   = (const float*)d_in[6];
    const float* rb1   = (const float*)d_in[7];
    const float* rw2   = (const float*)d_in[8];
    const float* rb2   = (const float*)d_in[9];
    float* out = (float*)d_out;

    __half *h16_p, *text2_p, *pretxt_p, *pimgb_p, *rw2h_p;
    float *logits_p;
    cudaGetSymbolAddress((void**)&h16_p,    g_h16);
    cudaGetSymbolAddress((void**)&logits_p, g_logits);
    cudaGetSymbolAddress((void**)&text2_p,  g_text2_h);
    cudaGetSymbolAddress((void**)&pretxt_p, g_pretxt_h);
    cudaGetSymbolAddress((void**)&pimgb_p,  g_pimgb_h);
    cudaGetSymbolAddress((void**)&rw2h_p,   g_rw2_h);

    dim3 blk128(128);
    dim3 gsmall(16, 4);   // 64x64 tiles over [256 x 1024]

    // rw2 -> fp16 (independent of the chain)
    convert_rw2<<<DD * DD / 1024, 256>>>(rw2, rw2h_p);
    // z=0: h16 = relu(text@aw1+ab1); z=1: pimgb = image@rw1[:D]+rb1
    small_pair<<<dim3(16, 4, 2), blk128>>>(
        text, aw1, ab1, h16_p, image, rw1, rb1, pimgb_p);
    // logits = h @ aw2 + ab2   (fp32 out for softmax)
    small_logits<<<gsmall, blk128>>>(h16_p, aw2, ab2, logits_p);
    // text2 = fp16(text * softmax(logits))
    softmax_mul<<<BSZ, 256>>>(logits_p, text, text2_p);
    // pretxt = fp16(text2 @ rw1[D:])
    small_pretxt<<<gsmall, blk128>>>(text2_p, rw1 + (size_t)DD * DD, pretxt_p);
    // big fused GEMM (round-4 structure, fp16 operands, f32 accum)
    big_gemm_mma<<<dim3(8, 512), 256>>>(
        pretxt_p, pimgb_p, rw2h_p, image, rb2, out);
}

// round 10
// speedup vs baseline: 2.0231x; 1.0106x over previous
#include <cuda_runtime.h>
#include <cuda_fp16.h>
#include <math.h>
#include <stdint.h>

#define DD 1024
#define BSZ 256

// ---- scratch globals --------------------------------------------------------
__device__ __half g_h16[BSZ * DD];
__device__ float  g_logits[BSZ * DD];
__device__ __half g_text2_h[BSZ * DD];
__device__ __half g_pretxt_h[BSZ * DD];
__device__ __half g_pimgb_h[BSZ * DD];
__device__ __half g_rw2_h[DD * DD];   // rw2 fp16, [k][n]

// ---- cp.async helpers ------------------------------------------------------
#define CP_ASYNC16(dst, src) \
    asm volatile("cp.async.cg.shared.global [%0], [%1], 16;" \
        :: "r"(dst), "l"(src) : "memory")
#define CP_COMMIT() asm volatile("cp.async.commit_group;" ::: "memory")
#define CP_WAIT0()  asm volatile("cp.async.wait_group 0;" ::: "memory")

// ---- mma.sync / ldmatrix ----------------------------------------------------
#define LDSM_X4(r0,r1,r2,r3,addr) \
    asm volatile("ldmatrix.sync.aligned.m8n8.x4.shared.b16 {%0,%1,%2,%3}, [%4];" \
        : "=r"(r0),"=r"(r1),"=r"(r2),"=r"(r3) : "r"(addr))
#define LDSM_X4_T(r0,r1,r2,r3,addr) \
    asm volatile("ldmatrix.sync.aligned.m8n8.x4.trans.shared.b16 {%0,%1,%2,%3}, [%4];" \
        : "=r"(r0),"=r"(r1),"=r"(r2),"=r"(r3) : "r"(addr))
#define MMA_F16F32(d0,d1,d2,d3,a0,a1,a2,a3,b0,b1) \
    asm volatile("mma.sync.aligned.m16n8k16.row.col.f32.f16.f16.f32 " \
        "{%0,%1,%2,%3}, {%4,%5,%6,%7}, {%8,%9}, {%0,%1,%2,%3};" \
        : "+f"(d0),"+f"(d1),"+f"(d2),"+f"(d3) \
        : "r"(a0),"r"(a1),"r"(a2),"r"(a3),"r"(b0),"r"(b1))

// pack 8 fp32 -> 8 fp16 (uint4)
__device__ __forceinline__ uint4 pack8(const float4 x, const float4 y)
{
    __half2 h0 = __floats2half2_rn(x.x, x.y);
    __half2 h1 = __floats2half2_rn(x.z, x.w);
    __half2 h2 = __floats2half2_rn(y.x, y.y);
    __half2 h3 = __floats2half2_rn(y.z, y.w);
    uint4 r;
    r.x = *(uint32_t*)&h0; r.y = *(uint32_t*)&h1;
    r.z = *(uint32_t*)&h2; r.w = *(uint32_t*)&h3;
    return r;
}

// ============================================================================
// Small-chain GEMMs on fp16 mma.sync (f32 accum), BK=64.
// C[256 x 1024] = A[256 x 1024] @ B[1024 x 1024] (+bias)(relu)
// CTA tile 64x64, BK=64, 128 threads = 4 warps (2m x 2n), warp tile 32x32.
// fp32 operands converted to fp16 in SMEM loaders (no prepass).
// Double-buffered, register prefetch, ONE __syncthreads per 64-K chunk.
// ============================================================================
template <bool A16, bool RELU, bool HAS_BIAS, bool HALFOUT>
__device__ __forceinline__ void hgemm64_body(
    const void* __restrict__ Aptr, const float* __restrict__ B,
    const float* __restrict__ bias, void* __restrict__ Cv)
{
    __shared__ __half As[2][64][72];   // [m][k], row 144B (36-bank rotation)
    __shared__ __half Bs[2][64][72];   // [k][n], row 144B

    const uint32_t STG = 64 * 72 * 2;  // 9216B per stage

    const int t    = threadIdx.x;
    const int lane = t & 31;
    const int warp = t >> 5;             // 0..3
    const int m0 = blockIdx.y * 64;
    const int n0 = blockIdx.x * 64;

    const int wm = (warp >> 1) * 32;     // 0 or 32
    const int wn = (warp & 1) * 32;      // 0 or 32

    // loaders: 2 threads per row, 32 cols each
    const int ar = t >> 1;               // A row / B k-row 0..63
    const int av = (t & 1) * 32;         // col start (elems)

    const float*  Af = (const float*)Aptr + (size_t)(m0 + ar) * DD + av;
    const __half* Ah = (const __half*)Aptr + (size_t)(m0 + ar) * DD + av;
    const float*  Brow = B + (size_t)ar * DD + n0 + av;

    const uint32_t aBase = (uint32_t)__cvta_generic_to_shared(
        &As[0][wm + ((lane >> 3) & 1) * 8 + (lane & 7)][(lane >> 4) * 8]);
    const uint32_t bBase = (uint32_t)__cvta_generic_to_shared(
        &Bs[0][((lane >> 3) & 1) * 8 + (lane & 7)][wn + (lane >> 4) * 8]);

    float acc[2][4][4] = {};

    float4 af[8]; uint4 ah[4];
    float4 bf[8];

    // ---- prologue: chunk 0 ----
    if (A16) {
        #pragma unroll
        for (int q = 0; q < 4; q++) ah[q] = *(const uint4*)(Ah + q * 8);
    } else {
        #pragma unroll
        for (int q = 0; q < 8; q++) af[q] = *(const float4*)(Af + q * 4);
    }
    #pragma unroll
    for (int q = 0; q < 8; q++) bf[q] = *(const float4*)(Brow + q * 4);
    {
        #pragma unroll
        for (int q = 0; q < 4; q++) {
            if (A16) *(uint4*)(&As[0][ar][av + q * 8]) = ah[q];
            else     *(uint4*)(&As[0][ar][av + q * 8]) = pack8(af[q*2], af[q*2+1]);
            *(uint4*)(&Bs[0][ar][av + q * 8]) = pack8(bf[q*2], bf[q*2+1]);
        }
    }
    __syncthreads();

    for (int c = 0; c < 16; c++) {
        const int s  = c & 1;
        const int ns = s ^ 1;
        const int kn = (c + 1) * 64;

        if (c < 15) {   // prefetch next chunk into registers
            if (A16) {
                #pragma unroll
                for (int q = 0; q < 4; q++) ah[q] = *(const uint4*)(Ah + kn + q * 8);
            } else {
                #pragma unroll
                for (int q = 0; q < 8; q++) af[q] = *(const float4*)(Af + kn + q * 4);
            }
            #pragma unroll
            for (int q = 0; q < 8; q++)
                bf[q] = *(const float4*)(Brow + (size_t)kn * DD + q * 4);
        }

        // ---- compute 4 k16 steps on stage s ----
        const uint32_t aB = aBase + s * STG;
        const uint32_t bB = bBase + s * STG;
        #pragma unroll
        for (int ks = 0; ks < 4; ks++) {
            const int kk = ks * 16;
            unsigned a[2][4];
            #pragma unroll
            for (int mt = 0; mt < 2; mt++)
                LDSM_X4(a[mt][0], a[mt][1], a[mt][2], a[mt][3],
                        aB + mt * 16 * 144 + kk * 2);
            unsigned b[4][2];
            #pragma unroll
            for (int bt = 0; bt < 2; bt++)
                LDSM_X4_T(b[bt*2][0], b[bt*2][1], b[bt*2+1][0], b[bt*2+1][1],
                          bB + kk * 144 + bt * 32);
            #pragma unroll
            for (int mt = 0; mt < 2; mt++)
                #pragma unroll
                for (int nt = 0; nt < 4; nt++)
                    MMA_F16F32(acc[mt][nt][0], acc[mt][nt][1],
                               acc[mt][nt][2], acc[mt][nt][3],
                               a[mt][0], a[mt][1], a[mt][2], a[mt][3],
                               b[nt][0], b[nt][1]);
        }

        if (c < 15) {   // store prefetched chunk into next stage
            #pragma unroll
            for (int q = 0; q < 4; q++) {
                if (A16) *(uint4*)(&As[ns][ar][av + q * 8]) = ah[q];
                else     *(uint4*)(&As[ns][ar][av + q * 8]) = pack8(af[q*2], af[q*2+1]);
                *(uint4*)(&Bs[ns][ar][av + q * 8]) = pack8(bf[q*2], bf[q*2+1]);
            }
        }
        __syncthreads();
    }

    // ---- epilogue ----
    #pragma unroll
    for (int mt = 0; mt < 2; mt++) {
        const int rbase = wm + mt * 16 + (lane >> 2);
        #pragma unroll
        for (int half = 0; half < 2; half++) {
            const int r = m0 + rbase + half * 8;
            #pragma unroll
            for (int nt = 0; nt < 4; nt++) {
                const int col = n0 + wn + nt * 8 + (lane & 3) * 2;
                float v0 = acc[mt][nt][half * 2 + 0];
                float v1 = acc[mt][nt][half * 2 + 1];
                if (HAS_BIAS) { v0 += bias[col]; v1 += bias[col + 1]; }
                if (RELU) { v0 = fmaxf(v0, 0.0f); v1 = fmaxf(v1, 0.0f); }
                if (HALFOUT) {
                    __half2 h = __floats2half2_rn(v0, v1);
                    *(uint32_t*)((__half*)Cv + (size_t)r * DD + col) =
                        *(uint32_t*)&h;
                } else {
                    float2 f = make_float2(v0, v1);
                    *(float2*)((float*)Cv + (size_t)r * DD + col) = f;
                }
            }
        }
    }
}

// z=0: h16 = fp16(relu(text@aw1+ab1))
// z=1: pimgb = fp16(image@rw1[:D]+rb1)
// z=2: rw2 -> fp16 conversion (64 blocks x 128 threads, 128 elems/thread)
__global__ void __launch_bounds__(128)
small_pair(const float* __restrict__ text, const float* __restrict__ aw1,
           const float* __restrict__ ab1, __half* __restrict__ h16,
           const float* __restrict__ image, const float* __restrict__ rw1,
           const float* __restrict__ rb1, __half* __restrict__ pimgb,
           const float* __restrict__ rw2, __half* __restrict__ rw2h)
{
    if (blockIdx.z == 0) {
        hgemm64_body<false, true, true, true>(text, aw1, ab1, h16);
    } else if (blockIdx.z == 1) {
        hgemm64_body<false, false, true, true>(image, rw1, rb1, pimgb);
    } else {
        const int blk = blockIdx.y * 16 + blockIdx.x;     // 0..63
        const int base = blk * 16384 + threadIdx.x * 4;
        #pragma unroll
        for (int q = 0; q < 32; q++) {
            const int idx = base + q * 512;
            float4 v = *(const float4*)(rw2 + idx);
            __half2 h0 = __floats2half2_rn(v.x, v.y);
            __half2 h1 = __floats2half2_rn(v.z, v.w);
            uint2 o; o.x = *(uint32_t*)&h0; o.y = *(uint32_t*)&h1;
            *(uint2*)(rw2h + idx) = o;
        }
    }
}

__global__ void __launch_bounds__(128)
small_logits(const __half* __restrict__ h16, const float* __restrict__ aw2,
             const float* __restrict__ ab2, float* __restrict__ logits)
{
    hgemm64_body<true, false, true, false>(h16, aw2, ab2, logits);
}

__global__ void __launch_bounds__(128)
small_pretxt(const __half* __restrict__ text2, const float* __restrict__ rw1b,
             __half* __restrict__ pretxt)
{
    hgemm64_body<true, false, false, true>(text2, rw1b, nullptr, pretxt);
}

// ---------------------------------------------------------------------------
// text2 = fp16(text * softmax(logits, axis=1))
__global__ void __launch_bounds__(256)
softmax_mul(const float* __restrict__ logits, const float* __restrict__ text,
            __half* __restrict__ out)
{
    const int row = blockIdx.x;
    const int t   = threadIdx.x;
    const float* l = logits + (size_t)row * DD;
    __shared__ float smax[8];
    __shared__ float ssum[8];

    float m = -1e30f;
    #pragma unroll
    for (int k = t; k < DD; k += 256) m = fmaxf(m, l[k]);
    #pragma unroll
    for (int o = 16; o > 0; o >>= 1)
        m = fmaxf(m, __shfl_xor_sync(0xffffffffu, m, o));
    if ((t & 31) == 0) smax[t >> 5] = m;
    __syncthreads();
    float rowmax = smax[0];
    #pragma unroll
    for (int w = 1; w < 8; w++) rowmax = fmaxf(rowmax, smax[w]);

    float s = 0.0f;
    #pragma unroll
    for (int k = t; k < DD; k += 256) s += expf(l[k] - rowmax);
    #pragma unroll
    for (int o = 16; o > 0; o >>= 1)
        s += __shfl_xor_sync(0xffffffffu, s, o);
    if ((t & 31) == 0) ssum[t >> 5] = s;
    __syncthreads();
    float tot = 0.0f;
    #pragma unroll
    for (int w = 0; w < 8; w++) tot += ssum[w];
    const float inv = 1.0f / tot;

    const float* tr = text + (size_t)row * DD;
    __half* orow = out + (size_t)row * DD;
    #pragma unroll
    for (int k = t * 2; k < DD; k += 512) {
        float w0 = tr[k]     * (expf(l[k]     - rowmax) * inv);
        float w1 = tr[k + 1] * (expf(l[k + 1] - rowmax) * inv);
        __half2 h = __floats2half2_rn(w0, w1);
        *(uint32_t*)(orow + k) = *(uint32_t*)&h;
    }
}

// ============================================================================
// Big GEMM on mma.sync (fp16 in, fp32 accum) — round-9 structure, unchanged
// (at the sm_103 register-MMA issue floor): CTA 128x128, BK=32, 8 warps
// (2m x 4n), warp tile 64x32, 2 CTAs/SM, double-buffered, cp.async for B,
// SMEM-side relu(pretxt+pimgb) A synthesis.
// ============================================================================
__device__ __forceinline__ uint4 fuse_relu_f16(uint4 p, uint4 t)
{
    const __half2 z = __float2half2_rn(0.0f);
    uint4 r;
    const __half2* pp = (const __half2*)&p;
    const __half2* tt = (const __half2*)&t;
    __half2* rr = (__half2*)&r;
    #pragma unroll
    for (int q = 0; q < 4; q++)
        rr[q] = __hmax2(__hadd2(pp[q], tt[q]), z);
    return r;
}

__global__ void __launch_bounds__(256, 2)
big_gemm_mma(const __half* __restrict__ pretxt,
             const __half* __restrict__ pimgb,
             const __half* __restrict__ rw2,
             const float* __restrict__ image,
             const float* __restrict__ rb2,
             float* __restrict__ out)
{
    __shared__ __half As[2][128][40];   // [m][k], 80B rows
    __shared__ __half Bs[2][32][136];   // [k][n], 272B rows

    const uint32_t ASTG = 128 * 40 * 2;
    const uint32_t BSTG = 32 * 136 * 2;

    const int t    = threadIdx.x;
    const int lane = t & 31;
    const int warp = t >> 5;
    const int n0 = blockIdx.x * 128;
    const int m0 = blockIdx.y * 128;
    const int i  = m0 >> 8;
    const int j0 = m0 & 255;

    const int wm = (warp >> 2) * 64;
    const int wn = (warp & 3) * 32;

    const int ar  = t >> 1;
    const int akv = (t & 1) * 16;
    const int br  = t >> 3;
    const int bnv = (t & 7) * 16;

    const __half* ptrow = pretxt + (size_t)i * DD;
    const __half* parow = pimgb + (size_t)(j0 + ar) * DD + akv;
    const __half* pbrow = rw2 + (size_t)br * DD + n0 + bnv;

    const uint32_t bdst0 = (uint32_t)__cvta_generic_to_shared(&Bs[0][br][bnv]);

    const uint32_t aBase = (uint32_t)__cvta_generic_to_shared(
        &As[0][wm + ((lane >> 3) & 1) * 8 + (lane & 7)][(lane >> 4) * 8]);
    const uint32_t bBase = (uint32_t)__cvta_generic_to_shared(
        &Bs[0][((lane >> 3) & 1) * 8 + (lane & 7)][wn + (lane >> 4) * 8]);

    float acc[4][4][4] = {};

    // --- prologue: chunk 0 into stage 0 ---
    CP_ASYNC16(bdst0,      pbrow);
    CP_ASYNC16(bdst0 + 16, pbrow + 8);
    CP_COMMIT();
    {
        uint4 pv0 = *(const uint4*)(parow);
        uint4 pv1 = *(const uint4*)(parow + 8);
        uint4 tv0 = *(const uint4*)(ptrow + akv);
        uint4 tv1 = *(const uint4*)(ptrow + akv + 8);
        *(uint4*)(&As[0][ar][akv])     = fuse_relu_f16(pv0, tv0);
        *(uint4*)(&As[0][ar][akv + 8]) = fuse_relu_f16(pv1, tv1);
    }
    CP_WAIT0();
    __syncthreads();

    uint4 pv0, pv1, tv0, tv1;
    for (int c = 0; c < 32; c++) {
        const int s  = c & 1;
        const int ns = s ^ 1;
        const int kn = (c + 1) * 32;

        if (c < 31) {
            CP_ASYNC16(bdst0 + ns * BSTG,      pbrow + (size_t)kn * DD);
            CP_ASYNC16(bdst0 + ns * BSTG + 16, pbrow + (size_t)kn * DD + 8);
            CP_COMMIT();
            pv0 = *(const uint4*)(parow + kn);
            pv1 = *(const uint4*)(parow + kn + 8);
            tv0 = *(const uint4*)(ptrow + kn + akv);
            tv1 = *(const uint4*)(ptrow + kn + akv + 8);
        }

        const uint32_t aB = aBase + s * ASTG;
        const uint32_t bB = bBase + s * BSTG;
        #pragma unroll
        for (int ks = 0; ks < 2; ks++) {
            const int kk = ks * 16;
            unsigned a[4][4];
            #pragma unroll
            for (int mt = 0; mt < 4; mt++)
                LDSM_X4(a[mt][0], a[mt][1], a[mt][2], a[mt][3],
                        aB + mt * 16 * 80 + kk * 2);
            unsigned b[4][2];
            #pragma unroll
            for (int bt = 0; bt < 2; bt++)
                LDSM_X4_T(b[bt*2][0], b[bt*2][1], b[bt*2+1][0], b[bt*2+1][1],
                          bB + kk * 272 + bt * 32);
            #pragma unroll
            for (int mt = 0; mt < 4; mt++)
                #pragma unroll
                for (int nt = 0; nt < 4; nt++)
                    MMA_F16F32(acc[mt][nt][0], acc[mt][nt][1],
                               acc[mt][nt][2], acc[mt][nt][3],
                               a[mt][0], a[mt][1], a[mt][2], a[mt][3],
                               b[nt][0], b[nt][1]);
        }

        if (c < 31) {
            *(uint4*)(&As[ns][ar][akv])     = fuse_relu_f16(pv0, tv0);
            *(uint4*)(&As[ns][ar][akv + 8]) = fuse_relu_f16(pv1, tv1);
            CP_WAIT0();
        }
        __syncthreads();
    }

    // ---- epilogue: + image[j] + rb2 ----
    #pragma unroll
    for (int mt = 0; mt < 4; mt++) {
        const int rbase = wm + mt * 16 + (lane >> 2);
        #pragma unroll
        for (int half = 0; half < 2; half++) {
            const int r = rbase + half * 8;
            const float* img = image + (size_t)(j0 + r) * DD;
            const size_t orow = (size_t)(m0 + r) * DD;
            #pragma unroll
            for (int nt = 0; nt < 4; nt++) {
                const int col = n0 + wn + nt * 8 + (lane & 3) * 2;
                float2 im = *(const float2*)(img + col);
                float2 rb = *(const float2*)(rb2 + col);
                float2 o;
                o.x = acc[mt][nt][half * 2 + 0] + im.x + rb.x;
                o.y = acc[mt][nt][half * 2 + 1] + im.y + rb.y;
                *(float2*)(out + orow + col) = o;
            }
        }
    }
}

// ---------------------------------------------------------------------------
extern "C" void kernel_launch(void* const* d_in, const int* in_sizes, int n_in,
                              void* d_out, int out_size)
{
    const float* image = (const float*)d_in[0];
    const float* text  = (const float*)d_in[1];
    const float* aw1   = (const float*)d_in[2];
    const float* ab1   = (const float*)d_in[3];
    const float* aw2   = (const float*)d_in[4];
    const float* ab2   = (const float*)d_in[5];
    const float* rw1   = (const float*)d_in[6];
    const float* rb1   = (const float*)d_in[7];
    const float* rw2   = (const float*)d_in[8];
    const float* rb2   = (const float*)d_in[9];
    float* out = (float*)d_out;

    __half *h16_p, *text2_p, *pretxt_p, *pimgb_p, *rw2h_p;
    float *logits_p;
    cudaGetSymbolAddress((void**)&h16_p,    g_h16);
    cudaGetSymbolAddress((void**)&logits_p, g_logits);
    cudaGetSymbolAddress((void**)&text2_p,  g_text2_h);
    cudaGetSymbolAddress((void**)&pretxt_p, g_pretxt_h);
    cudaGetSymbolAddress((void**)&pimgb_p,  g_pimgb_h);
    cudaGetSymbolAddress((void**)&rw2h_p,   g_rw2_h);

    dim3 blk128(128);
    dim3 gsmall(16, 4);   // 64x64 tiles over [256 x 1024]

    // z=0: h16; z=1: pimgb; z=2: rw2->fp16 (merged, one launch)
    small_pair<<<dim3(16, 4, 3), blk128>>>(
        text, aw1, ab1, h16_p, image, rw1, rb1, pimgb_p, rw2, rw2h_p);
    // logits = h @ aw2 + ab2   (fp32 out for softmax)
    small_logits<<<gsmall, blk128>>>(h16_p, aw2, ab2, logits_p);
    // text2 = fp16(text * softmax(logits))
    softmax_mul<<<BSZ, 256>>>(logits_p, text, text2_p);
    // pretxt = fp16(text2 @ rw1[D:])
    small_pretxt<<<gsmall, blk128>>>(text2_p, rw1 + (size_t)DD * DD, pretxt_p);
    // big fused GEMM (round-9 structure, fp16 operands, f32 accum)
    big_gemm_mma<<<dim3(8, 512), 256>>>(
        pretxt_p, pimgb_p, rw2h_p, image, rb2, out);
}

// round 12
// speedup vs baseline: 2.1861x; 1.0806x over previous
#include <cuda_runtime.h>
#include <cuda_fp16.h>
#include <math.h>
#include <stdint.h>

#define DD 1024
#define BSZ 256

// ---- scratch globals --------------------------------------------------------
__device__ __half g_h16[BSZ * DD];
__device__ float  g_logits[BSZ * DD];
__device__ __half g_text2_h[BSZ * DD];
__device__ __half g_pretxt_h[BSZ * DD];
__device__ __half g_pimgb_h[BSZ * DD];
__device__ __half g_rw2_h[DD * DD];    // rw2 fp16 [k][n]
__device__ __half g_aw1_h[DD * DD];
__device__ __half g_aw2_h[DD * DD];
__device__ __half g_rw1_h[2 * DD * DD];
__device__ __half g_text_h[BSZ * DD];
__device__ __half g_img_h[BSZ * DD];

// ---- cp.async helpers ------------------------------------------------------
#define CP_ASYNC16(dst, src) \
    asm volatile("cp.async.cg.shared.global [%0], [%1], 16;" \
        :: "r"(dst), "l"(src) : "memory")
#define CP_COMMIT() asm volatile("cp.async.commit_group;" ::: "memory")
#define CP_WAIT0()  asm volatile("cp.async.wait_group 0;" ::: "memory")
#define CP_WAIT2()  asm volatile("cp.async.wait_group 2;" ::: "memory")

// ---- mma.sync / ldmatrix ----------------------------------------------------
#define LDSM_X4(r0,r1,r2,r3,addr) \
    asm volatile("ldmatrix.sync.aligned.m8n8.x4.shared.b16 {%0,%1,%2,%3}, [%4];" \
        : "=r"(r0),"=r"(r1),"=r"(r2),"=r"(r3) : "r"(addr))
#define LDSM_X4_T(r0,r1,r2,r3,addr) \
    asm volatile("ldmatrix.sync.aligned.m8n8.x4.trans.shared.b16 {%0,%1,%2,%3}, [%4];" \
        : "=r"(r0),"=r"(r1),"=r"(r2),"=r"(r3) : "r"(addr))
#define MMA_F16F32(d0,d1,d2,d3,a0,a1,a2,a3,b0,b1) \
    asm volatile("mma.sync.aligned.m16n8k16.row.col.f32.f16.f16.f32 " \
        "{%0,%1,%2,%3}, {%4,%5,%6,%7}, {%8,%9}, {%0,%1,%2,%3};" \
        : "+f"(d0),"+f"(d1),"+f"(d2),"+f"(d3) \
        : "r"(a0),"r"(a1),"r"(a2),"r"(a3),"r"(b0),"r"(b1))

// ============================================================================
// Prepass: convert all fp32 operands to fp16 (one launch, fully parallel).
// Segments: [0,1024) aw1 | [1024,2048) aw2 | [2048,4096) rw1 |
// [4096,5120) rw2 | [5120,5376) text | [5376,5632) image. 1024 elems/block.
// ============================================================================
__global__ void __launch_bounds__(256)
conv_all(const float* __restrict__ aw1, const float* __restrict__ aw2,
         const float* __restrict__ rw1, const float* __restrict__ rw2,
         const float* __restrict__ text, const float* __restrict__ image,
         __half* __restrict__ aw1h, __half* __restrict__ aw2h,
         __half* __restrict__ rw1h, __half* __restrict__ rw2h,
         __half* __restrict__ texth, __half* __restrict__ imgh)
{
    const int b = blockIdx.x;
    const float* src; __half* dst; int off;
    if      (b < 1024) { src = aw1;   dst = aw1h;  off = b; }
    else if (b < 2048) { src = aw2;   dst = aw2h;  off = b - 1024; }
    else if (b < 4096) { src = rw1;   dst = rw1h;  off = b - 2048; }
    else if (b < 5120) { src = rw2;   dst = rw2h;  off = b - 4096; }
    else if (b < 5376) { src = text;  dst = texth; off = b - 5120; }
    else               { src = image; dst = imgh;  off = b - 5376; }
    const int idx = off * 1024 + threadIdx.x * 4;
    float4 v = *(const float4*)(src + idx);
    __half2 h0 = __floats2half2_rn(v.x, v.y);
    __half2 h1 = __floats2half2_rn(v.z, v.w);
    uint2 o; o.x = *(uint32_t*)&h0; o.y = *(uint32_t*)&h1;
    *(uint2*)(dst + idx) = o;
}

// ============================================================================
// Small-chain GEMMs: all-fp16 operands, 4-stage cp.async pipeline.
// C[256 x 1024] = A[256 x 1024] @ B[1024 x 1024] (+bias)(relu)
// CTA 64x64, BK=32, 32 chunks (FULL K=1024), 128 threads = 4 warps (2m x 2n),
// warp tile 32x32. One __syncthreads per chunk; loads run 3 chunks ahead.
// ============================================================================
template <bool RELU, bool HAS_BIAS, bool HALFOUT>
__device__ __forceinline__ void hgemm_ms(
    const __half* __restrict__ A, const __half* __restrict__ B,
    const float* __restrict__ bias, void* __restrict__ Cv)
{
    __shared__ __half As[4][64][40];   // [m][k], row 80B; 5120B/stage
    __shared__ __half Bs[4][32][72];   // [k][n], row 144B; 4608B/stage

    const int t    = threadIdx.x;
    const int lane = t & 31;
    const int warp = t >> 5;             // 0..3
    const int m0 = blockIdx.y * 64;
    const int n0 = blockIdx.x * 64;

    const int wm = (warp >> 1) * 32;     // 0 or 32
    const int wn = (warp & 1) * 32;      // 0 or 32

    // loaders: A 64rx32k (2 thr/row, 32B each); B 32kx64n (4 thr/row, 32B each)
    const int ar = t >> 1;               // 0..63
    const int ac = (t & 1) * 16;         // 0 or 16 (elems)
    const int br = t >> 2;               // 0..31
    const int bc = (t & 3) * 16;         // 0..48 (elems)

    const __half* Arow = A + (size_t)(m0 + ar) * DD + ac;
    const __half* Brow = B + (size_t)br * DD + n0 + bc;

    const uint32_t adst0 = (uint32_t)__cvta_generic_to_shared(&As[0][ar][ac]);
    const uint32_t bdst0 = (uint32_t)__cvta_generic_to_shared(&Bs[0][br][bc]);

    const uint32_t aBase = (uint32_t)__cvta_generic_to_shared(
        &As[0][wm + ((lane >> 3) & 1) * 8 + (lane & 7)][(lane >> 4) * 8]);
    const uint32_t bBase = (uint32_t)__cvta_generic_to_shared(
        &Bs[0][((lane >> 3) & 1) * 8 + (lane & 7)][wn + (lane >> 4) * 8]);

    float acc[2][4][4] = {};

    // ---- prologue: issue chunks 0..2 into slots 0..2 ----
    #pragma unroll
    for (int q = 0; q < 3; q++) {
        const uint32_t ad = adst0 + q * 5120;
        const uint32_t bd = bdst0 + q * 4608;
        const __half* as = Arow + q * 32;
        const __half* bs = Brow + (size_t)(q * 32) * DD;
        CP_ASYNC16(ad,      as);
        CP_ASYNC16(ad + 16, as + 8);
        CP_ASYNC16(bd,      bs);
        CP_ASYNC16(bd + 16, bs + 8);
        CP_COMMIT();
    }

    for (int c = 0; c < 32; c++) {       // FULL K: 32 chunks of 32
        CP_WAIT2();          // chunk c complete (≤2 newer groups outstanding)
        __syncthreads();     // all warps done with slot (c-1)&3; data visible

        if (c < 29) {        // issue chunk c+3 into slot (c+3)&3
            const int q = c + 3;
            const uint32_t ad = adst0 + (q & 3) * 5120;
            const uint32_t bd = bdst0 + (q & 3) * 4608;
            const __half* as = Arow + q * 32;
            const __half* bs = Brow + (size_t)(q * 32) * DD;
            CP_ASYNC16(ad,      as);
            CP_ASYNC16(ad + 16, as + 8);
            CP_ASYNC16(bd,      bs);
            CP_ASYNC16(bd + 16, bs + 8);
        }
        CP_COMMIT();         // always commit (empty groups keep numbering)

        // ---- compute slot c&3 ----
        const uint32_t aB = aBase + (c & 3) * 5120;
        const uint32_t bB = bBase + (c & 3) * 4608;
        #pragma unroll
        for (int ks = 0; ks < 2; ks++) {
            const int kk = ks * 16;
            unsigned a[2][4];
            #pragma unroll
            for (int mt = 0; mt < 2; mt++)
                LDSM_X4(a[mt][0], a[mt][1], a[mt][2], a[mt][3],
                        aB + mt * 16 * 80 + kk * 2);
            unsigned b[4][2];
            #pragma unroll
            for (int bt = 0; bt < 2; bt++)
                LDSM_X4_T(b[bt*2][0], b[bt*2][1], b[bt*2+1][0], b[bt*2+1][1],
                          bB + kk * 144 + bt * 32);
            #pragma unroll
            for (int mt = 0; mt < 2; mt++)
                #pragma unroll
                for (int nt = 0; nt < 4; nt++)
                    MMA_F16F32(acc[mt][nt][0], acc[mt][nt][1],
                               acc[mt][nt][2], acc[mt][nt][3],
                               a[mt][0], a[mt][1], a[mt][2], a[mt][3],
                               b[nt][0], b[nt][1]);
        }
    }

    // ---- epilogue ----
    #pragma unroll
    for (int mt = 0; mt < 2; mt++) {
        const int rbase = wm + mt * 16 + (lane >> 2);
        #pragma unroll
        for (int half = 0; half < 2; half++) {
            const int r = m0 + rbase + half * 8;
            #pragma unroll
            for (int nt = 0; nt < 4; nt++) {
                const int col = n0 + wn + nt * 8 + (lane & 3) * 2;
                float v0 = acc[mt][nt][half * 2 + 0];
                float v1 = acc[mt][nt][half * 2 + 1];
                if (HAS_BIAS) { v0 += bias[col]; v1 += bias[col + 1]; }
                if (RELU) { v0 = fmaxf(v0, 0.0f); v1 = fmaxf(v1, 0.0f); }
                if (HALFOUT) {
                    __half2 h = __floats2half2_rn(v0, v1);
                    *(uint32_t*)((__half*)Cv + (size_t)r * DD + col) =
                        *(uint32_t*)&h;
                } else {
                    float2 f = make_float2(v0, v1);
                    *(float2*)((float*)Cv + (size_t)r * DD + col) = f;
                }
            }
        }
    }
}

// z=0: h16 = fp16(relu(text16@aw1+ab1));  z=1: pimgb = fp16(img16@rw1a+rb1)
__global__ void __launch_bounds__(128)
small_pair(const __half* __restrict__ text16, const __half* __restrict__ aw1h,
           const float* __restrict__ ab1, __half* __restrict__ h16,
           const __half* __restrict__ img16, const __half* __restrict__ rw1h,
           const float* __restrict__ rb1, __half* __restrict__ pimgb)
{
    if (blockIdx.z == 0)
        hgemm_ms<true, true, true>(text16, aw1h, ab1, h16);
    else
        hgemm_ms<false, true, true>(img16, rw1h, rb1, pimgb);
}

__global__ void __launch_bounds__(128)
small_logits(const __half* __restrict__ h16, const __half* __restrict__ aw2h,
             const float* __restrict__ ab2, float* __restrict__ logits)
{
    hgemm_ms<false, true, false>(h16, aw2h, ab2, logits);
}

__global__ void __launch_bounds__(128)
small_pretxt(const __half* __restrict__ text2, const __half* __restrict__ rw1bh,
             __half* __restrict__ pretxt)
{
    hgemm_ms<false, false, true>(text2, rw1bh, nullptr, pretxt);
}

// ---------------------------------------------------------------------------
// text2 = fp16(text * softmax(logits, axis=1))
__global__ void __launch_bounds__(256)
softmax_mul(const float* __restrict__ logits, const float* __restrict__ text,
            __half* __restrict__ out)
{
    const int row = blockIdx.x;
    const int t   = threadIdx.x;
    const float* l = logits + (size_t)row * DD;
    __shared__ float smax[8];
    __shared__ float ssum[8];

    float m = -1e30f;
    #pragma unroll
    for (int k = t; k < DD; k += 256) m = fmaxf(m, l[k]);
    #pragma unroll
    for (int o = 16; o > 0; o >>= 1)
        m = fmaxf(m, __shfl_xor_sync(0xffffffffu, m, o));
    if ((t & 31) == 0) smax[t >> 5] = m;
    __syncthreads();
    float rowmax = smax[0];
    #pragma unroll
    for (int w = 1; w < 8; w++) rowmax = fmaxf(rowmax, smax[w]);

    float s = 0.0f;
    #pragma unroll
    for (int k = t; k < DD; k += 256) s += expf(l[k] - rowmax);
    #pragma unroll
    for (int o = 16; o > 0; o >>= 1)
        s += __shfl_xor_sync(0xffffffffu, s, o);
    if ((t & 31) == 0) ssum[t >> 5] = s;
    __syncthreads();
    float tot = 0.0f;
    #pragma unroll
    for (int w = 0; w < 8; w++) tot += ssum[w];
    const float inv = 1.0f / tot;

    const float* tr = text + (size_t)row * DD;
    __half* orow = out + (size_t)row * DD;
    #pragma unroll
    for (int k = t * 2; k < DD; k += 512) {
        float w0 = tr[k]     * (expf(l[k]     - rowmax) * inv);
        float w1 = tr[k + 1] * (expf(l[k + 1] - rowmax) * inv);
        __half2 h = __floats2half2_rn(w0, w1);
        *(uint32_t*)(orow + k) = *(uint32_t*)&h;
    }
}

// ============================================================================
// Big GEMM on mma.sync (fp16 in, fp32 accum) — round-9/10 structure, unchanged
// (at the sm_103 register-MMA issue floor): CTA 128x128, BK=32, 8 warps
// (2m x 4n), warp tile 64x32, 2 CTAs/SM, double-buffered, cp.async for B,
// SMEM-side relu(pretxt+pimgb) A synthesis.
// ============================================================================
__device__ __forceinline__ uint4 fuse_relu_f16(uint4 p, uint4 t)
{
    const __half2 z = __float2half2_rn(0.0f);
    uint4 r;
    const __half2* pp = (const __half2*)&p;
    const __half2* tt = (const __half2*)&t;
    __half2* rr = (__half2*)&r;
    #pragma unroll
    for (int q = 0; q < 4; q++)
        rr[q] = __hmax2(__hadd2(pp[q], tt[q]), z);
    return r;
}

__global__ void __launch_bounds__(256, 2)
big_gemm_mma(const __half* __restrict__ pretxt,
             const __half* __restrict__ pimgb,
             const __half* __restrict__ rw2,
             const float* __restrict__ image,
             const float* __restrict__ rb2,
             float* __restrict__ out)
{
    __shared__ __half As[2][128][40];   // [m][k], 80B rows
    __shared__ __half Bs[2][32][136];   // [k][n], 272B rows

    const uint32_t ASTG = 128 * 40 * 2;
    const uint32_t BSTG = 32 * 136 * 2;

    const int t    = threadIdx.x;
    const int lane = t & 31;
    const int warp = t >> 5;
    const int n0 = blockIdx.x * 128;
    const int m0 = blockIdx.y * 128;
    const int i  = m0 >> 8;
    const int j0 = m0 & 255;

    const int wm = (warp >> 2) * 64;
    const int wn = (warp & 3) * 32;

    const int ar  = t >> 1;
    const int akv = (t & 1) * 16;
    const int br  = t >> 3;
    const int bnv = (t & 7) * 16;

    const __half* ptrow = pretxt + (size_t)i * DD;
    const __half* parow = pimgb + (size_t)(j0 + ar) * DD + akv;
    const __half* pbrow = rw2 + (size_t)br * DD + n0 + bnv;

    const uint32_t bdst0 = (uint32_t)__cvta_generic_to_shared(&Bs[0][br][bnv]);

    const uint32_t aBase = (uint32_t)__cvta_generic_to_shared(
        &As[0][wm + ((lane >> 3) & 1) * 8 + (lane & 7)][(lane >> 4) * 8]);
    const uint32_t bBase = (uint32_t)__cvta_generic_to_shared(
        &Bs[0][((lane >> 3) & 1) * 8 + (lane & 7)][wn + (lane >> 4) * 8]);

    float acc[4][4][4] = {};

    // --- prologue: chunk 0 into stage 0 ---
    CP_ASYNC16(bdst0,      pbrow);
    CP_ASYNC16(bdst0 + 16, pbrow + 8);
    CP_COMMIT();
    {
        uint4 pv0 = *(const uint4*)(parow);
        uint4 pv1 = *(const uint4*)(parow + 8);
        uint4 tv0 = *(const uint4*)(ptrow + akv);
        uint4 tv1 = *(const uint4*)(ptrow + akv + 8);
        *(uint4*)(&As[0][ar][akv])     = fuse_relu_f16(pv0, tv0);
        *(uint4*)(&As[0][ar][akv + 8]) = fuse_relu_f16(pv1, tv1);
    }
    CP_WAIT0();
    __syncthreads();

    uint4 pv0, pv1, tv0, tv1;
    for (int c = 0; c < 32; c++) {
        const int s  = c & 1;
        const int ns = s ^ 1;
        const int kn = (c + 1) * 32;

        if (c < 31) {
            CP_ASYNC16(bdst0 + ns * BSTG,      pbrow + (size_t)kn * DD);
            CP_ASYNC16(bdst0 + ns * BSTG + 16, pbrow + (size_t)kn * DD + 8);
            CP_COMMIT();
            pv0 = *(const uint4*)(parow + kn);
            pv1 = *(const uint4*)(parow + kn + 8);
            tv0 = *(const uint4*)(ptrow + kn + akv);
            tv1 = *(const uint4*)(ptrow + kn + akv + 8);
        }

        const uint32_t aB = aBase + s * ASTG;
        const uint32_t bB = bBase + s * BSTG;
        #pragma unroll
        for (int ks = 0; ks < 2; ks++) {
            const int kk = ks * 16;
            unsigned a[4][4];
            #pragma unroll
            for (int mt = 0; mt < 4; mt++)
                LDSM_X4(a[mt][0], a[mt][1], a[mt][2], a[mt][3],
                        aB + mt * 16 * 80 + kk * 2);
            unsigned b[4][2];
            #pragma unroll
            for (int bt = 0; bt < 2; bt++)
                LDSM_X4_T(b[bt*2][0], b[bt*2][1], b[bt*2+1][0], b[bt*2+1][1],
                          bB + kk * 272 + bt * 32);
            #pragma unroll
            for (int mt = 0; mt < 4; mt++)
                #pragma unroll
                for (int nt = 0; nt < 4; nt++)
                    MMA_F16F32(acc[mt][nt][0], acc[mt][nt][1],
                               acc[mt][nt][2], acc[mt][nt][3],
                               a[mt][0], a[mt][1], a[mt][2], a[mt][3],
                               b[nt][0], b[nt][1]);
        }

        if (c < 31) {
            *(uint4*)(&As[ns][ar][akv])     = fuse_relu_f16(pv0, tv0);
            *(uint4*)(&As[ns][ar][akv + 8]) = fuse_relu_f16(pv1, tv1);
            CP_WAIT0();
        }
        __syncthreads();
    }

    // ---- epilogue: + image[j] + rb2 ----
    #pragma unroll
    for (int mt = 0; mt < 4; mt++) {
        const int rbase = wm + mt * 16 + (lane >> 2);
        #pragma unroll
        for (int half = 0; half < 2; half++) {
            const int r = rbase + half * 8;
            const float* img = image + (size_t)(j0 + r) * DD;
            const size_t orow = (size_t)(m0 + r) * DD;
            #pragma unroll
            for (int nt = 0; nt < 4; nt++) {
                const int col = n0 + wn + nt * 8 + (lane & 3) * 2;
                float2 im = *(const float2*)(img + col);
                float2 rb = *(const float2*)(rb2 + col);
                float2 o;
                o.x = acc[mt][nt][half * 2 + 0] + im.x + rb.x;
                o.y = acc[mt][nt][half * 2 + 1] + im.y + rb.y;
                *(float2*)(out + orow + col) = o;
            }
        }
    }
}

// ---------------------------------------------------------------------------
extern "C" void kernel_launch(void* const* d_in, const int* in_sizes, int n_in,
                              void* d_out, int out_size)
{
    const float* image = (const float*)d_in[0];
    const float* text  = (const float*)d_in[1];
    const float* aw1   = (const float*)d_in[2];
    const float* ab1   = (const float*)d_in[3];
    const float* aw2   = (const float*)d_in[4];
    const float* ab2   = (const float*)d_in[5];
    const float* rw1   = (const float*)d_in[6];
    const float* rb1   = (const float*)d_in[7];
    const float* rw2   = (const float*)d_in[8];
    const float* rb2   = (const float*)d_in[9];
    float* out = (float*)d_out;

    __half *h16_p, *text2_p, *pretxt_p, *pimgb_p, *rw2h_p;
    __half *aw1h_p, *aw2h_p, *rw1h_p, *texth_p, *imgh_p;
    float *logits_p;
    cudaGetSymbolAddress((void**)&h16_p,    g_h16);
    cudaGetSymbolAddress((void**)&logits_p, g_logits);
    cudaGetSymbolAddress((void**)&text2_p,  g_text2_h);
    cudaGetSymbolAddress((void**)&pretxt_p, g_pretxt_h);
    cudaGetSymbolAddress((void**)&pimgb_p,  g_pimgb_h);
    cudaGetSymbolAddress((void**)&rw2h_p,   g_rw2_h);
    cudaGetSymbolAddress((void**)&aw1h_p,   g_aw1_h);
    cudaGetSymbolAddress((void**)&aw2h_p,   g_aw2_h);
    cudaGetSymbolAddress((void**)&rw1h_p,   g_rw1_h);
    cudaGetSymbolAddress((void**)&texth_p,  g_text_h);
    cudaGetSymbolAddress((void**)&imgh_p,   g_img_h);

    dim3 blk128(128);
    dim3 gsmall(16, 4);   // 64x64 tiles over [256 x 1024]

    // prepass: convert all fp32 operands to fp16 (one launch)
    conv_all<<<5632, 256>>>(aw1, aw2, rw1, rw2, text, image,
                            aw1h_p, aw2h_p, rw1h_p, rw2h_p, texth_p, imgh_p);
    // z=0: h16 = relu(text@aw1+ab1); z=1: pimgb = image@rw1[:D]+rb1
    small_pair<<<dim3(16, 4, 2), blk128>>>(
        texth_p, aw1h_p, ab1, h16_p, imgh_p, rw1h_p, rb1, pimgb_p);
    // logits = h @ aw2 + ab2   (fp32 out for softmax)
    small_logits<<<gsmall, blk128>>>(h16_p, aw2h_p, ab2, logits_p);
    // text2 = fp16(text * softmax(logits))
    softmax_mul<<<BSZ, 256>>>(logits_p, text, text2_p);
    // pretxt = fp16(text2 @ rw1[D:])
    small_pretxt<<<gsmall, blk128>>>(text2_p, rw1h_p + (size_t)DD * DD, pretxt_p);
    // big fused GEMM (round-9/10 structure, fp16 operands, f32 accum)
    big_gemm_mma<<<dim3(8, 512), 256>>>(
        pretxt_p, pimgb_p, rw2h_p, image, rb2, out);
}

// round 13
// speedup vs baseline: 2.1950x; 1.0041x over previous
#include <cuda_runtime.h>
#include <cuda_fp16.h>
#include <math.h>
#include <stdint.h>

#define DD 1024
#define BSZ 256

// ---- scratch globals --------------------------------------------------------
__device__ __half g_h16[BSZ * DD];
__device__ float  g_logits[BSZ * DD];
__device__ __half g_text2_h[BSZ * DD];
__device__ __half g_pretxt_h[BSZ * DD];
__device__ __half g_pimgb_h[BSZ * DD];
__device__ __half g_rw2_h[DD * DD];    // rw2 fp16 [k][n]
__device__ __half g_aw1_h[DD * DD];
__device__ __half g_aw2_h[DD * DD];
__device__ __half g_rw1_h[2 * DD * DD];
__device__ __half g_text_h[BSZ * DD];
__device__ __half g_img_h[BSZ * DD];

// ---- cp.async helpers ------------------------------------------------------
#define CP_ASYNC16(dst, src) \
    asm volatile("cp.async.cg.shared.global [%0], [%1], 16;" \
        :: "r"(dst), "l"(src) : "memory")
#define CP_COMMIT() asm volatile("cp.async.commit_group;" ::: "memory")
#define CP_WAIT0()  asm volatile("cp.async.wait_group 0;" ::: "memory")
#define CP_WAIT2()  asm volatile("cp.async.wait_group 2;" ::: "memory")

// ---- mma.sync / ldmatrix ----------------------------------------------------
#define LDSM_X4(r0,r1,r2,r3,addr) \
    asm volatile("ldmatrix.sync.aligned.m8n8.x4.shared.b16 {%0,%1,%2,%3}, [%4];" \
        : "=r"(r0),"=r"(r1),"=r"(r2),"=r"(r3) : "r"(addr))
#define LDSM_X4_T(r0,r1,r2,r3,addr) \
    asm volatile("ldmatrix.sync.aligned.m8n8.x4.trans.shared.b16 {%0,%1,%2,%3}, [%4];" \
        : "=r"(r0),"=r"(r1),"=r"(r2),"=r"(r3) : "r"(addr))
#define MMA_F16F32(d0,d1,d2,d3,a0,a1,a2,a3,b0,b1) \
    asm volatile("mma.sync.aligned.m16n8k16.row.col.f32.f16.f16.f32 " \
        "{%0,%1,%2,%3}, {%4,%5,%6,%7}, {%8,%9}, {%0,%1,%2,%3};" \
        : "+f"(d0),"+f"(d1),"+f"(d2),"+f"(d3) \
        : "r"(a0),"r"(a1),"r"(a2),"r"(a3),"r"(b0),"r"(b1))

// ============================================================================
// Prepass: convert all fp32 operands to fp16 (one launch, fully parallel).
// Segments: [0,1024) aw1 | [1024,2048) aw2 | [2048,4096) rw1 |
// [4096,5120) rw2 | [5120,5376) text | [5376,5632) image. 1024 elems/block.
// ============================================================================
__global__ void __launch_bounds__(256)
conv_all(const float* __restrict__ aw1, const float* __restrict__ aw2,
         const float* __restrict__ rw1, const float* __restrict__ rw2,
         const float* __restrict__ text, const float* __restrict__ image,
         __half* __restrict__ aw1h, __half* __restrict__ aw2h,
         __half* __restrict__ rw1h, __half* __restrict__ rw2h,
         __half* __restrict__ texth, __half* __restrict__ imgh)
{
    const int b = blockIdx.x;
    const float* src; __half* dst; int off;
    if      (b < 1024) { src = aw1;   dst = aw1h;  off = b; }
    else if (b < 2048) { src = aw2;   dst = aw2h;  off = b - 1024; }
    else if (b < 4096) { src = rw1;   dst = rw1h;  off = b - 2048; }
    else if (b < 5120) { src = rw2;   dst = rw2h;  off = b - 4096; }
    else if (b < 5376) { src = text;  dst = texth; off = b - 5120; }
    else               { src = image; dst = imgh;  off = b - 5376; }
    const int idx = off * 1024 + threadIdx.x * 4;
    float4 v = *(const float4*)(src + idx);
    __half2 h0 = __floats2half2_rn(v.x, v.y);
    __half2 h1 = __floats2half2_rn(v.z, v.w);
    uint2 o; o.x = *(uint32_t*)&h0; o.y = *(uint32_t*)&h1;
    *(uint2*)(dst + idx) = o;
}

// ============================================================================
// Small-chain GEMMs: all-fp16, 4-stage cp.async pipeline, 32x64 CTA tile.
// C[256 x 1024] = A[256 x 1024] @ B[1024 x 1024] (+bias)(relu)
// Grid (16,8) = 128 CTAs; 128 threads = 4 warps (2m x 2n), warp tile 16x32.
// One __syncthreads per 32-K chunk; loads run 3 chunks ahead.
// Accumulation order per output element identical to round 12 (bitwise same).
// ============================================================================
template <bool RELU, bool HAS_BIAS, bool HALFOUT>
__device__ __forceinline__ void hgemm_ms(
    const __half* __restrict__ A, const __half* __restrict__ B,
    const float* __restrict__ bias, void* __restrict__ Cv)
{
    __shared__ __half As[4][32][40];   // [m][k], row 80B; 2560B/stage
    __shared__ __half Bs[4][32][72];   // [k][n], row 144B; 4608B/stage

    const int t    = threadIdx.x;
    const int lane = t & 31;
    const int warp = t >> 5;             // 0..3
    const int m0 = blockIdx.y * 32;
    const int n0 = blockIdx.x * 64;

    const int wm = (warp >> 1) * 16;     // 0 or 16
    const int wn = (warp & 1) * 32;      // 0 or 32

    // loaders: A 32r x 32k (4 thr/row, 16B each); B 32k x 64n (4 thr/row, 32B)
    const int ar = t >> 2;               // 0..31
    const int ac = (t & 3) * 8;          // 0,8,16,24 (elems)
    const int br = t >> 2;               // 0..31
    const int bc = (t & 3) * 16;         // 0..48 (elems)

    const __half* Arow = A + (size_t)(m0 + ar) * DD + ac;
    const __half* Brow = B + (size_t)br * DD + n0 + bc;

    const uint32_t adst0 = (uint32_t)__cvta_generic_to_shared(&As[0][ar][ac]);
    const uint32_t bdst0 = (uint32_t)__cvta_generic_to_shared(&Bs[0][br][bc]);

    const uint32_t aBase = (uint32_t)__cvta_generic_to_shared(
        &As[0][wm + ((lane >> 3) & 1) * 8 + (lane & 7)][(lane >> 4) * 8]);
    const uint32_t bBase = (uint32_t)__cvta_generic_to_shared(
        &Bs[0][((lane >> 3) & 1) * 8 + (lane & 7)][wn + (lane >> 4) * 8]);

    float acc[4][4] = {};   // [nt][reg] (single m-tile of 16)

    // ---- prologue: issue chunks 0..2 into slots 0..2 ----
    #pragma unroll
    for (int q = 0; q < 3; q++) {
        const uint32_t ad = adst0 + q * 2560;
        const uint32_t bd = bdst0 + q * 4608;
        const __half* as = Arow + q * 32;
        const __half* bs = Brow + (size_t)(q * 32) * DD;
        CP_ASYNC16(ad, as);
        CP_ASYNC16(bd,      bs);
        CP_ASYNC16(bd + 16, bs + 8);
        CP_COMMIT();
    }

    for (int c = 0; c < 32; c++) {       // FULL K: 32 chunks of 32
        CP_WAIT2();          // chunk c complete (≤2 newer groups outstanding)
        __syncthreads();     // all warps done with slot (c-1)&3; data visible

        if (c < 29) {        // issue chunk c+3 into slot (c+3)&3
            const int q = c + 3;
            const uint32_t ad = adst0 + (q & 3) * 2560;
            const uint32_t bd = bdst0 + (q & 3) * 4608;
            const __half* as = Arow + q * 32;
            const __half* bs = Brow + (size_t)(q * 32) * DD;
            CP_ASYNC16(ad, as);
            CP_ASYNC16(bd,      bs);
            CP_ASYNC16(bd + 16, bs + 8);
        }
        CP_COMMIT();         // always commit (keeps group numbering)

        // ---- compute slot c&3 ----
        const uint32_t aB = aBase + (c & 3) * 2560;
        const uint32_t bB = bBase + (c & 3) * 4608;
        #pragma unroll
        for (int ks = 0; ks < 2; ks++) {
            const int kk = ks * 16;
            unsigned a[4];
            LDSM_X4(a[0], a[1], a[2], a[3], aB + kk * 2);
            unsigned b[4][2];
            #pragma unroll
            for (int bt = 0; bt < 2; bt++)
                LDSM_X4_T(b[bt*2][0], b[bt*2][1], b[bt*2+1][0], b[bt*2+1][1],
                          bB + kk * 144 + bt * 32);
            #pragma unroll
            for (int nt = 0; nt < 4; nt++)
                MMA_F16F32(acc[nt][0], acc[nt][1], acc[nt][2], acc[nt][3],
                           a[0], a[1], a[2], a[3], b[nt][0], b[nt][1]);
        }
    }

    // ---- epilogue ----
    const int rbase = wm + (lane >> 2);
    #pragma unroll
    for (int half = 0; half < 2; half++) {
        const int r = m0 + rbase + half * 8;
        #pragma unroll
        for (int nt = 0; nt < 4; nt++) {
            const int col = n0 + wn + nt * 8 + (lane & 3) * 2;
            float v0 = acc[nt][half * 2 + 0];
            float v1 = acc[nt][half * 2 + 1];
            if (HAS_BIAS) { v0 += bias[col]; v1 += bias[col + 1]; }
            if (RELU) { v0 = fmaxf(v0, 0.0f); v1 = fmaxf(v1, 0.0f); }
            if (HALFOUT) {
                __half2 h = __floats2half2_rn(v0, v1);
                *(uint32_t*)((__half*)Cv + (size_t)r * DD + col) = *(uint32_t*)&h;
            } else {
                float2 f = make_float2(v0, v1);
                *(float2*)((float*)Cv + (size_t)r * DD + col) = f;
            }
        }
    }
}

// z=0: h16 = fp16(relu(text16@aw1+ab1));  z=1: pimgb = fp16(img16@rw1a+rb1)
__global__ void __launch_bounds__(128)
small_pair(const __half* __restrict__ text16, const __half* __restrict__ aw1h,
           const float* __restrict__ ab1, __half* __restrict__ h16,
           const __half* __restrict__ img16, const __half* __restrict__ rw1h,
           const float* __restrict__ rb1, __half* __restrict__ pimgb)
{
    if (blockIdx.z == 0)
        hgemm_ms<true, true, true>(text16, aw1h, ab1, h16);
    else
        hgemm_ms<false, true, true>(img16, rw1h, rb1, pimgb);
}

__global__ void __launch_bounds__(128)
small_logits(const __half* __restrict__ h16, const __half* __restrict__ aw2h,
             const float* __restrict__ ab2, float* __restrict__ logits)
{
    hgemm_ms<false, true, false>(h16, aw2h, ab2, logits);
}

__global__ void __launch_bounds__(128)
small_pretxt(const __half* __restrict__ text2, const __half* __restrict__ rw1bh,
             __half* __restrict__ pretxt)
{
    hgemm_ms<false, false, true>(text2, rw1bh, nullptr, pretxt);
}

// ---------------------------------------------------------------------------
// text2 = fp16(text * softmax(logits, axis=1))
__global__ void __launch_bounds__(256)
softmax_mul(const float* __restrict__ logits, const float* __restrict__ text,
            __half* __restrict__ out)
{
    const int row = blockIdx.x;
    const int t   = threadIdx.x;
    const float* l = logits + (size_t)row * DD;
    __shared__ float smax[8];
    __shared__ float ssum[8];

    float m = -1e30f;
    #pragma unroll
    for (int k = t; k < DD; k += 256) m = fmaxf(m, l[k]);
    #pragma unroll
    for (int o = 16; o > 0; o >>= 1)
        m = fmaxf(m, __shfl_xor_sync(0xffffffffu, m, o));
    if ((t & 31) == 0) smax[t >> 5] = m;
    __syncthreads();
    float rowmax = smax[0];
    #pragma unroll
    for (int w = 1; w < 8; w++) rowmax = fmaxf(rowmax, smax[w]);

    float s = 0.0f;
    #pragma unroll
    for (int k = t; k < DD; k += 256) s += expf(l[k] - rowmax);
    #pragma unroll
    for (int o = 16; o > 0; o >>= 1)
        s += __shfl_xor_sync(0xffffffffu, s, o);
    if ((t & 31) == 0) ssum[t >> 5] = s;
    __syncthreads();
    float tot = 0.0f;
    #pragma unroll
    for (int w = 0; w < 8; w++) tot += ssum[w];
    const float inv = 1.0f / tot;

    const float* tr = text + (size_t)row * DD;
    __half* orow = out + (size_t)row * DD;
    #pragma unroll
    for (int k = t * 2; k < DD; k += 512) {
        float w0 = tr[k]     * (expf(l[k]     - rowmax) * inv);
        float w1 = tr[k + 1] * (expf(l[k + 1] - rowmax) * inv);
        __half2 h = __floats2half2_rn(w0, w1);
        *(uint32_t*)(orow + k) = *(uint32_t*)&h;
    }
}

// ============================================================================
// Big GEMM on mma.sync (fp16 in, fp32 accum) — unchanged (at the sm_103
// register-MMA issue floor): CTA 128x128, BK=32, 8 warps (2m x 4n),
// warp tile 64x32, 2 CTAs/SM, double-buffered, cp.async for B,
// SMEM-side relu(pretxt+pimgb) A synthesis.
// ============================================================================
__device__ __forceinline__ uint4 fuse_relu_f16(uint4 p, uint4 t)
{
    const __half2 z = __float2half2_rn(0.0f);
    uint4 r;
    const __half2* pp = (const __half2*)&p;
    const __half2* tt = (const __half2*)&t;
    __half2* rr = (__half2*)&r;
    #pragma unroll
    for (int q = 0; q < 4; q++)
        rr[q] = __hmax2(__hadd2(pp[q], tt[q]), z);
    return r;
}

__global__ void __launch_bounds__(256, 2)
big_gemm_mma(const __half* __restrict__ pretxt,
             const __half* __restrict__ pimgb,
             const __half* __restrict__ rw2,
             const float* __restrict__ image,
             const float* __restrict__ rb2,
             float* __restrict__ out)
{
    __shared__ __half As[2][128][40];   // [m][k], 80B rows
    __shared__ __half Bs[2][32][136];   // [k][n], 272B rows

    const uint32_t ASTG = 128 * 40 * 2;
    const uint32_t BSTG = 32 * 136 * 2;

    const int t    = threadIdx.x;
    const int lane = t & 31;
    const int warp = t >> 5;
    const int n0 = blockIdx.x * 128;
    const int m0 = blockIdx.y * 128;
    const int i  = m0 >> 8;
    const int j0 = m0 & 255;

    const int wm = (warp >> 2) * 64;
    const int wn = (warp & 3) * 32;

    const int ar  = t >> 1;
    const int akv = (t & 1) * 16;
    const int br  = t >> 3;
    const int bnv = (t & 7) * 16;

    const __half* ptrow = pretxt + (size_t)i * DD;
    const __half* parow = pimgb + (size_t)(j0 + ar) * DD + akv;
    const __half* pbrow = rw2 + (size_t)br * DD + n0 + bnv;

    const uint32_t bdst0 = (uint32_t)__cvta_generic_to_shared(&Bs[0][br][bnv]);

    const uint32_t aBase = (uint32_t)__cvta_generic_to_shared(
        &As[0][wm + ((lane >> 3) & 1) * 8 + (lane & 7)][(lane >> 4) * 8]);
    const uint32_t bBase = (uint32_t)__cvta_generic_to_shared(
        &Bs[0][((lane >> 3) & 1) * 8 + (lane & 7)][wn + (lane >> 4) * 8]);

    float acc[4][4][4] = {};

    // --- prologue: chunk 0 into stage 0 ---
    CP_ASYNC16(bdst0,      pbrow);
    CP_ASYNC16(bdst0 + 16, pbrow + 8);
    CP_COMMIT();
    {
        uint4 pv0 = *(const uint4*)(parow);
        uint4 pv1 = *(const uint4*)(parow + 8);
        uint4 tv0 = *(const uint4*)(ptrow + akv);
        uint4 tv1 = *(const uint4*)(ptrow + akv + 8);
        *(uint4*)(&As[0][ar][akv])     = fuse_relu_f16(pv0, tv0);
        *(uint4*)(&As[0][ar][akv + 8]) = fuse_relu_f16(pv1, tv1);
    }
    CP_WAIT0();
    __syncthreads();

    uint4 pv0, pv1, tv0, tv1;
    for (int c = 0; c < 32; c++) {
        const int s  = c & 1;
        const int ns = s ^ 1;
        const int kn = (c + 1) * 32;

        if (c < 31) {
            CP_ASYNC16(bdst0 + ns * BSTG,      pbrow + (size_t)kn * DD);
            CP_ASYNC16(bdst0 + ns * BSTG + 16, pbrow + (size_t)kn * DD + 8);
            CP_COMMIT();
            pv0 = *(const uint4*)(parow + kn);
            pv1 = *(const uint4*)(parow + kn + 8);
            tv0 = *(const uint4*)(ptrow + kn + akv);
            tv1 = *(const uint4*)(ptrow + kn + akv + 8);
        }

        const uint32_t aB = aBase + s * ASTG;
        const uint32_t bB = bBase + s * BSTG;
        #pragma unroll
        for (int ks = 0; ks < 2; ks++) {
            const int kk = ks * 16;
            unsigned a[4][4];
            #pragma unroll
            for (int mt = 0; mt < 4; mt++)
                LDSM_X4(a[mt][0], a[mt][1], a[mt][2], a[mt][3],
                        aB + mt * 16 * 80 + kk * 2);
            unsigned b[4][2];
            #pragma unroll
            for (int bt = 0; bt < 2; bt++)
                LDSM_X4_T(b[bt*2][0], b[bt*2][1], b[bt*2+1][0], b[bt*2+1][1],
                          bB + kk * 272 + bt * 32);
            #pragma unroll
            for (int mt = 0; mt < 4; mt++)
                #pragma unroll
                for (int nt = 0; nt < 4; nt++)
                    MMA_F16F32(acc[mt][nt][0], acc[mt][nt][1],
                               acc[mt][nt][2], acc[mt][nt][3],
                               a[mt][0], a[mt][1], a[mt][2], a[mt][3],
                               b[nt][0], b[nt][1]);
        }

        if (c < 31) {
            *(uint4*)(&As[ns][ar][akv])     = fuse_relu_f16(pv0, tv0);
            *(uint4*)(&As[ns][ar][akv + 8]) = fuse_relu_f16(pv1, tv1);
            CP_WAIT0();
        }
        __syncthreads();
    }

    // ---- epilogue: + image[j] + rb2 ----
    #pragma unroll
    for (int mt = 0; mt < 4; mt++) {
        const int rbase = wm + mt * 16 + (lane >> 2);
        #pragma unroll
        for (int half = 0; half < 2; half++) {
            const int r = rbase + half * 8;
            const float* img = image + (size_t)(j0 + r) * DD;
            const size_t orow = (size_t)(m0 + r) * DD;
            #pragma unroll
            for (int nt = 0; nt < 4; nt++) {
                const int col = n0 + wn + nt * 8 + (lane & 3) * 2;
                float2 im = *(const float2*)(img + col);
                float2 rb = *(const float2*)(rb2 + col);
                float2 o;
                o.x = acc[mt][nt][half * 2 + 0] + im.x + rb.x;
                o.y = acc[mt][nt][half * 2 + 1] + im.y + rb.y;
                *(float2*)(out + orow + col) = o;
            }
        }
    }
}

// ---------------------------------------------------------------------------
extern "C" void kernel_launch(void* const* d_in, const int* in_sizes, int n_in,
                              void* d_out, int out_size)
{
    const float* image = (const float*)d_in[0];
    const float* text  = (const float*)d_in[1];
    const float* aw1   = (const float*)d_in[2];
    const float* ab1   = (const float*)d_in[3];
    const float* aw2   = (const float*)d_in[4];
    const float* ab2   = (const float*)d_in[5];
    const float* rw1   = (const float*)d_in[6];
    const float* rb1   = (const float*)d_in[7];
    const float* rw2   = (const float*)d_in[8];
    const float* rb2   = (const float*)d_in[9];
    float* out = (float*)d_out;

    __half *h16_p, *text2_p, *pretxt_p, *pimgb_p, *rw2h_p;
    __half *aw1h_p, *aw2h_p, *rw1h_p, *texth_p, *imgh_p;
    float *logits_p;
    cudaGetSymbolAddress((void**)&h16_p,    g_h16);
    cudaGetSymbolAddress((void**)&logits_p, g_logits);
    cudaGetSymbolAddress((void**)&text2_p,  g_text2_h);
    cudaGetSymbolAddress((void**)&pretxt_p, g_pretxt_h);
    cudaGetSymbolAddress((void**)&pimgb_p,  g_pimgb_h);
    cudaGetSymbolAddress((void**)&rw2h_p,   g_rw2_h);
    cudaGetSymbolAddress((void**)&aw1h_p,   g_aw1_h);
    cudaGetSymbolAddress((void**)&aw2h_p,   g_aw2_h);
    cudaGetSymbolAddress((void**)&rw1h_p,   g_rw1_h);
    cudaGetSymbolAddress((void**)&texth_p,  g_text_h);
    cudaGetSymbolAddress((void**)&imgh_p,   g_img_h);

    dim3 blk128(128);
    dim3 gsmall(16, 8);   // 32x64 tiles over [256 x 1024] -> 128 CTAs

    // prepass: convert all fp32 operands to fp16 (one launch)
    conv_all<<<5632, 256>>>(aw1, aw2, rw1, rw2, text, image,
                            aw1h_p, aw2h_p, rw1h_p, rw2h_p, texth_p, imgh_p);
    // z=0: h16 = relu(text@aw1+ab1); z=1: pimgb = image@rw1[:D]+rb1
    small_pair<<<dim3(16, 8, 2), blk128>>>(
        texth_p, aw1h_p, ab1, h16_p, imgh_p, rw1h_p, rb1, pimgb_p);
    // logits = h @ aw2 + ab2   (fp32 out for softmax)
    small_logits<<<gsmall, blk128>>>(h16_p, aw2h_p, ab2, logits_p);
    // text2 = fp16(text * softmax(logits))
    softmax_mul<<<BSZ, 256>>>(logits_p, text, text2_p);
    // pretxt = fp16(text2 @ rw1[D:])
    small_pretxt<<<gsmall, blk128>>>(text2_p, rw1h_p + (size_t)DD * DD, pretxt_p);
    // big fused GEMM (unchanged, at register-HMMA floor)
    big_gemm_mma<<<dim3(8, 512), 256>>>(
        pretxt_p, pimgb_p, rw2h_p, image, rb2, out);
}